// round 2
// baseline (speedup 1.0000x reference)
#include <cuda_runtime.h>
#include <math.h>

// Problem constants
#define BATCH 2
#define SEQ   2048
#define EMB   1024
#define NH    16
#define HD    64
#define FFD   4096
#define MTOK  (BATCH*SEQ)     // 4096
#define QKV_N (3*EMB)         // 3072
#define LN_EPS 1e-5f

// Scratch (device globals; allocations are forbidden in kernel_launch).
// Live ranges:
//   g_xn  : LN1 out -> consumed by QKV gemm; then reused as LN2 out (xn2)
//   g_qkv : QKV out -> consumed by attn
//   g_att : attn out -> consumed by proj
//   g_x2  : residual-1 out -> consumed by LN2, FFN2 epilogue
//   g_h   : FFN1 out -> consumed by FFN2
__device__ float g_xn [MTOK*EMB];     // 16 MB (also used as xn2)
__device__ float g_qkv[MTOK*QKV_N];   // 48 MB
__device__ float g_att[MTOK*EMB];     // 16 MB
__device__ float g_x2 [MTOK*EMB];     // 16 MB
__device__ float g_h  [MTOK*FFD];     // 64 MB

// ---------------------------------------------------------------------------
// LayerNorm: one block per row of EMB=1024, 256 threads, 4 elems/thread
// ---------------------------------------------------------------------------
__global__ __launch_bounds__(256) void ln_kernel(const float* __restrict__ x,
                                                 const float* __restrict__ g,
                                                 const float* __restrict__ b,
                                                 float* __restrict__ out)
{
    int row = blockIdx.x;
    const float* xr = x + (size_t)row * EMB;
    float v[4];
    float sum = 0.f, sq = 0.f;
#pragma unroll
    for (int i = 0; i < 4; i++) {
        v[i] = xr[threadIdx.x + i * 256];
        sum += v[i];
        sq  += v[i] * v[i];
    }
#pragma unroll
    for (int o = 16; o > 0; o >>= 1) {
        sum += __shfl_xor_sync(0xffffffffu, sum, o);
        sq  += __shfl_xor_sync(0xffffffffu, sq,  o);
    }
    __shared__ float s1[8], s2[8];
    int w = threadIdx.x >> 5, l = threadIdx.x & 31;
    if (l == 0) { s1[w] = sum; s2[w] = sq; }
    __syncthreads();
    sum = 0.f; sq = 0.f;
#pragma unroll
    for (int i = 0; i < 8; i++) { sum += s1[i]; sq += s2[i]; }
    float mu  = sum * (1.0f / EMB);
    float var = sq * (1.0f / EMB) - mu * mu;
    float inv = rsqrtf(var + LN_EPS);
    float* orow = out + (size_t)row * EMB;
#pragma unroll
    for (int i = 0; i < 4; i++) {
        int c = threadIdx.x + i * 256;
        orow[c] = (v[i] - mu) * inv * g[c] + b[c];
    }
}

// ---------------------------------------------------------------------------
// SGEMM 128x128x8, 256 threads, 8x8 per thread. Row-major A[M,K], B[K,N].
// EPI: 0 = none, 1 = +bias +res, 2 = +bias then exact GELU
// Requires M%128==0, N%128==0, K%8==0 (all shapes here satisfy this).
// ---------------------------------------------------------------------------
template <int EPI>
__global__ __launch_bounds__(256, 2) void sgemm(const float* __restrict__ A,
                                                const float* __restrict__ B,
                                                float* __restrict__ C,
                                                const float* __restrict__ bias,
                                                const float* __restrict__ res,
                                                int M, int N, int K)
{
    __shared__ float As[8][128];
    __shared__ float Bs[8][128];

    int tid = threadIdx.x;
    int m0 = blockIdx.y * 128;
    int n0 = blockIdx.x * 128;

    int la_m = tid >> 1;
    int la_k = (tid & 1) * 4;
    int lb_k = tid >> 5;
    int lb_n = (tid & 31) * 4;

    const float* Ap = A + (size_t)(m0 + la_m) * K + la_k;
    const float* Bp = B + (size_t)lb_k * N + n0 + lb_n;

    int rx = tid & 15;
    int ry = tid >> 4;

    float acc[8][8];
#pragma unroll
    for (int i = 0; i < 8; i++)
#pragma unroll
        for (int j = 0; j < 8; j++) acc[i][j] = 0.f;

    for (int k0 = 0; k0 < K; k0 += 8) {
        float4 av = *(const float4*)Ap;  Ap += 8;
        float4 bv = *(const float4*)Bp;  Bp += (size_t)8 * N;
        As[la_k + 0][la_m] = av.x;
        As[la_k + 1][la_m] = av.y;
        As[la_k + 2][la_m] = av.z;
        As[la_k + 3][la_m] = av.w;
        *(float4*)&Bs[lb_k][lb_n] = bv;
        __syncthreads();
#pragma unroll
        for (int kk = 0; kk < 8; kk++) {
            float4 a0 = *(const float4*)&As[kk][ry * 8];
            float4 a1 = *(const float4*)&As[kk][ry * 8 + 4];
            float4 b0 = *(const float4*)&Bs[kk][rx * 8];
            float4 b1 = *(const float4*)&Bs[kk][rx * 8 + 4];
            float af[8] = {a0.x, a0.y, a0.z, a0.w, a1.x, a1.y, a1.z, a1.w};
            float bf[8] = {b0.x, b0.y, b0.z, b0.w, b1.x, b1.y, b1.z, b1.w};
#pragma unroll
            for (int i = 0; i < 8; i++)
#pragma unroll
                for (int j = 0; j < 8; j++) acc[i][j] += af[i] * bf[j];
        }
        __syncthreads();
    }

#pragma unroll
    for (int i = 0; i < 8; i++) {
        int row = m0 + ry * 8 + i;
        float* Cp = C + (size_t)row * N + n0 + rx * 8;
        const float* Rp = (EPI == 1) ? (res + (size_t)row * N + n0 + rx * 8) : nullptr;
#pragma unroll
        for (int j = 0; j < 8; j++) {
            float v = acc[i][j];
            if (EPI >= 1) v += bias[n0 + rx * 8 + j];
            if (EPI == 1) v += Rp[j];
            if (EPI == 2) v = 0.5f * v * (1.0f + erff(v * 0.70710678118654752f));
            Cp[j] = v;
        }
    }
}

// ---------------------------------------------------------------------------
// Flash-style attention.  grid = (SEQ/64, NH, BATCH), 256 threads.
// qkv layout: [b, n, 3*EMB], q at col h*64+d, k at EMB + h*64+d, v at 2*EMB.
// logits = (q.k) * D^0.25 (reference divides by sqrt(scale), scale=D^-0.5)
// ---------------------------------------------------------------------------
__global__ __launch_bounds__(256, 1) void attn_kernel(const float* __restrict__ qkv,
                                                      float* __restrict__ out)
{
    __shared__ float Qs[64][64];
    __shared__ float Ks[64][64];   // reused as P after S is computed
    __shared__ float Vs[64][64];

    int qb = blockIdx.x;
    int h  = blockIdx.y;
    int b  = blockIdx.z;
    int tid = threadIdx.x;
    int tx = tid & 15;
    int ty = tid >> 4;

    const float SCL = 2.8284271247461903f;  // 64^0.25
    const float* base = qkv + (size_t)b * SEQ * QKV_N + h * HD;

    // Load Q tile (scaled)
    for (int idx = tid; idx < 64 * 64; idx += 256) {
        int r = idx >> 6, d = idx & 63;
        Qs[r][d] = base[(size_t)(qb * 64 + r) * QKV_N + d] * SCL;
    }

    float m_run[4], l_run[4];
    float o_acc[4][4];
#pragma unroll
    for (int i = 0; i < 4; i++) {
        m_run[i] = -1e30f; l_run[i] = 0.f;
#pragma unroll
        for (int j = 0; j < 4; j++) o_acc[i][j] = 0.f;
    }

    for (int kt = 0; kt < SEQ / 64; kt++) {
        __syncthreads();   // protect Ks/Vs (and Qs on first iter) reuse
        for (int idx = tid; idx < 64 * 64; idx += 256) {
            int r = idx >> 6, d = idx & 63;
            int sw = ((r >> 2) & 7) << 2;                 // bank-conflict swizzle
            Ks[r][d ^ sw] = base[EMB     + (size_t)(kt * 64 + r) * QKV_N + d];
            Vs[r][d]      = base[2 * EMB + (size_t)(kt * 64 + r) * QKV_N + d];
        }
        __syncthreads();

        // S = Q * K^T  (64x64 tile, thread owns rows ty*4.., cols tx*4..)
        float s[4][4];
#pragma unroll
        for (int i = 0; i < 4; i++)
#pragma unroll
            for (int j = 0; j < 4; j++) s[i][j] = 0.f;

        for (int d = 0; d < 64; d++) {
            float qf[4], kf[4];
#pragma unroll
            for (int i = 0; i < 4; i++) qf[i] = Qs[ty * 4 + i][d];
#pragma unroll
            for (int j = 0; j < 4; j++) {
                int kr = tx * 4 + j;
                kf[j] = Ks[kr][d ^ (((kr >> 2) & 7) << 2)];
            }
#pragma unroll
            for (int i = 0; i < 4; i++)
#pragma unroll
                for (int j = 0; j < 4; j++) s[i][j] += qf[i] * kf[j];
        }

        // Online softmax per row (reduction across tx: 16-lane shfl groups)
#pragma unroll
        for (int i = 0; i < 4; i++) {
            float rm = fmaxf(fmaxf(s[i][0], s[i][1]), fmaxf(s[i][2], s[i][3]));
#pragma unroll
            for (int o = 1; o < 16; o <<= 1)
                rm = fmaxf(rm, __shfl_xor_sync(0xffffffffu, rm, o));
            float mnew = fmaxf(m_run[i], rm);
            float corr = __expf(m_run[i] - mnew);
            float rs = 0.f;
#pragma unroll
            for (int j = 0; j < 4; j++) {
                s[i][j] = __expf(s[i][j] - mnew);
                rs += s[i][j];
            }
#pragma unroll
            for (int o = 1; o < 16; o <<= 1)
                rs += __shfl_xor_sync(0xffffffffu, rs, o);
            l_run[i] = l_run[i] * corr + rs;
            m_run[i] = mnew;
#pragma unroll
            for (int j = 0; j < 4; j++) o_acc[i][j] *= corr;
        }

        // Write P into Ks buffer (natural layout), then PV
        __syncthreads();
#pragma unroll
        for (int i = 0; i < 4; i++)
#pragma unroll
            for (int j = 0; j < 4; j++) Ks[ty * 4 + i][tx * 4 + j] = s[i][j];
        __syncthreads();

        for (int kk = 0; kk < 64; kk++) {
            float pf[4], vf[4];
#pragma unroll
            for (int i = 0; i < 4; i++) pf[i] = Ks[ty * 4 + i][kk];
#pragma unroll
            for (int j = 0; j < 4; j++) vf[j] = Vs[kk][tx * 4 + j];
#pragma unroll
            for (int i = 0; i < 4; i++)
#pragma unroll
                for (int j = 0; j < 4; j++) o_acc[i][j] += pf[i] * vf[j];
        }
    }

    // Normalize and write out[b, q, h*64 + d]
#pragma unroll
    for (int i = 0; i < 4; i++) {
        float inv = 1.0f / l_run[i];
        int qrow = qb * 64 + ty * 4 + i;
        float* op = out + (size_t)(b * SEQ + qrow) * EMB + h * HD + tx * 4;
#pragma unroll
        for (int j = 0; j < 4; j++) op[j] = o_acc[i][j] * inv;
    }
}

// ---------------------------------------------------------------------------
// Launch: LN1 -> QKV -> attn -> proj(+res) -> LN2 -> FFN1(gelu) -> FFN2(+res)
// ---------------------------------------------------------------------------
extern "C" void kernel_launch(void* const* d_in, const int* in_sizes, int n_in,
                              void* d_out, int out_size)
{
    const float* x     = (const float*)d_in[0];
    const float* w_qkv = (const float*)d_in[1];
    const float* w_out = (const float*)d_in[2];
    const float* b_out = (const float*)d_in[3];
    const float* ln1_g = (const float*)d_in[4];
    const float* ln1_b = (const float*)d_in[5];
    const float* ln2_g = (const float*)d_in[6];
    const float* ln2_b = (const float*)d_in[7];
    const float* w1    = (const float*)d_in[8];
    const float* b1    = (const float*)d_in[9];
    const float* w2    = (const float*)d_in[10];
    const float* b2    = (const float*)d_in[11];
    float* out = (float*)d_out;

    float *p_xn, *p_qkv, *p_att, *p_x2, *p_h;
    cudaGetSymbolAddress((void**)&p_xn,  g_xn);
    cudaGetSymbolAddress((void**)&p_qkv, g_qkv);
    cudaGetSymbolAddress((void**)&p_att, g_att);
    cudaGetSymbolAddress((void**)&p_x2,  g_x2);
    cudaGetSymbolAddress((void**)&p_h,   g_h);
    float* p_xn2 = p_xn;   // LN1 output dead after QKV gemm; reuse for LN2 out

    // 1. LN1
    ln_kernel<<<MTOK, 256>>>(x, ln1_g, ln1_b, p_xn);
    // 2. QKV GEMM: [4096,1024] @ [1024,3072]
    sgemm<0><<<dim3(QKV_N / 128, MTOK / 128), 256>>>(p_xn, w_qkv, p_qkv,
                                                     nullptr, nullptr,
                                                     MTOK, QKV_N, EMB);
    // 3. Attention
    attn_kernel<<<dim3(SEQ / 64, NH, BATCH), 256>>>(p_qkv, p_att);
    // 4. Output projection + bias + residual(x)
    sgemm<1><<<dim3(EMB / 128, MTOK / 128), 256>>>(p_att, w_out, p_x2,
                                                   b_out, x,
                                                   MTOK, EMB, EMB);
    // 5. LN2
    ln_kernel<<<MTOK, 256>>>(p_x2, ln2_g, ln2_b, p_xn2);
    // 6. FFN1 + bias + exact GELU
    sgemm<2><<<dim3(FFD / 128, MTOK / 128), 256>>>(p_xn2, w1, p_h,
                                                   b1, nullptr,
                                                   MTOK, FFD, EMB);
    // 7. FFN2 + bias + residual(x2) -> out
    sgemm<1><<<dim3(EMB / 128, MTOK / 128), 256>>>(p_h, w2, out,
                                                   b2, p_x2,
                                                   MTOK, EMB, FFD);
}

// round 4
// speedup vs baseline: 1.7578x; 1.7578x over previous
#include <cuda_runtime.h>
#include <math.h>
#include <stdint.h>

// Problem constants
#define BATCH 2
#define SEQ   2048
#define EMB   1024
#define NH    16
#define HD    64
#define FFD   4096
#define MTOK  (BATCH*SEQ)     // 4096
#define QKV_N (3*EMB)         // 3072
#define LN_EPS 1e-5f

// Scratch (device globals; allocations are forbidden in kernel_launch).
__device__ float g_xn [MTOK*EMB];     // LN1 out; reused as LN2 out
__device__ float g_qkv[MTOK*QKV_N];
__device__ float g_att[MTOK*EMB];
__device__ float g_x2 [MTOK*EMB];
__device__ float g_h  [MTOK*FFD];

// ---------------------------------------------------------------------------
// LayerNorm: one block per row of EMB=1024, 256 threads, 4 elems/thread
// ---------------------------------------------------------------------------
__global__ __launch_bounds__(256) void ln_kernel(const float* __restrict__ x,
                                                 const float* __restrict__ g,
                                                 const float* __restrict__ b,
                                                 float* __restrict__ out)
{
    int row = blockIdx.x;
    const float* xr = x + (size_t)row * EMB;
    float v[4];
    float sum = 0.f, sq = 0.f;
#pragma unroll
    for (int i = 0; i < 4; i++) {
        v[i] = xr[threadIdx.x + i * 256];
        sum += v[i];
        sq  += v[i] * v[i];
    }
#pragma unroll
    for (int o = 16; o > 0; o >>= 1) {
        sum += __shfl_xor_sync(0xffffffffu, sum, o);
        sq  += __shfl_xor_sync(0xffffffffu, sq,  o);
    }
    __shared__ float s1[8], s2[8];
    int w = threadIdx.x >> 5, l = threadIdx.x & 31;
    if (l == 0) { s1[w] = sum; s2[w] = sq; }
    __syncthreads();
    sum = 0.f; sq = 0.f;
#pragma unroll
    for (int i = 0; i < 8; i++) { sum += s1[i]; sq += s2[i]; }
    float mu  = sum * (1.0f / EMB);
    float var = sq * (1.0f / EMB) - mu * mu;
    float inv = rsqrtf(var + LN_EPS);
    float* orow = out + (size_t)row * EMB;
#pragma unroll
    for (int i = 0; i < 4; i++) {
        int c = threadIdx.x + i * 256;
        orow[c] = (v[i] - mu) * inv * g[c] + b[c];
    }
}

// ---------------------------------------------------------------------------
// tf32 tensor-core GEMM: 128x128x16 CTA tile, 8 warps (2x4), warp tile 64x32,
// mma.sync.m16n8k8.tf32, double-buffered smem, fp32 accumulate.
// A[M,K], B[K,N] row-major.  EPI: 0 none, 1 +bias+res, 2 +bias+GELU(exact)
// Requires M%128==0, N%128==0, K%16==0.
// ---------------------------------------------------------------------------
#define SA 20    // As row stride (uint32): banks (20*g + t3) conflict-free
#define SB 136   // Bs row stride (uint32): banks (8*t3 + g) conflict-free

__device__ __forceinline__ uint32_t f2tf(float f)
{
    uint32_t r;
    asm("cvt.rna.tf32.f32 %0, %1;" : "=r"(r) : "f"(f));
    return r;
}

__device__ __forceinline__ void mma_tf32(float* d, const uint32_t* a, const uint32_t* b)
{
    asm volatile(
        "mma.sync.aligned.m16n8k8.row.col.f32.tf32.tf32.f32 "
        "{%0,%1,%2,%3}, {%4,%5,%6,%7}, {%8,%9}, {%0,%1,%2,%3};\n"
        : "+f"(d[0]), "+f"(d[1]), "+f"(d[2]), "+f"(d[3])
        : "r"(a[0]), "r"(a[1]), "r"(a[2]), "r"(a[3]), "r"(b[0]), "r"(b[1]));
}

template <int EPI>
__global__ __launch_bounds__(256) void sgemm_tc(const float* __restrict__ A,
                                                const float* __restrict__ B,
                                                float* __restrict__ C,
                                                const float* __restrict__ bias,
                                                const float* __restrict__ res,
                                                int M, int N, int K)
{
    __shared__ uint32_t As[2][128][SA];
    __shared__ uint32_t Bs[2][16][SB];

    const int tid = threadIdx.x;
    const int m0 = blockIdx.y * 128;
    const int n0 = blockIdx.x * 128;

    const int warpId = tid >> 5;
    const int lane   = tid & 31;
    const int wm = (warpId & 1) * 64;   // warp m offset
    const int wn = (warpId >> 1) * 32;  // warp n offset
    const int g  = lane >> 2;           // group id 0..7
    const int t3 = lane & 3;            // thread-in-group 0..3

    // Global-load mapping (2 float4 each for A and B per thread)
    const int amA0 = (tid) >> 2,        akA0 = ((tid) & 3) << 2;
    const int amA1 = (tid + 256) >> 2,  akA1 = ((tid + 256) & 3) << 2;
    const int bkB0 = (tid) >> 5,        bnB0 = ((tid) & 31) << 2;
    const int bkB1 = (tid + 256) >> 5,  bnB1 = ((tid + 256) & 31) << 2;

    float acc[4][4][4];
#pragma unroll
    for (int i = 0; i < 4; i++)
#pragma unroll
        for (int j = 0; j < 4; j++)
#pragma unroll
            for (int c = 0; c < 4; c++) acc[i][j][c] = 0.f;

    const int T = K >> 4;   // number of 16-wide k tiles
    float4 ra0, ra1, rb0, rb1;

    // prefetch tile 0
    {
        const int k0 = 0;
        ra0 = *(const float4*)&A[(size_t)(m0 + amA0) * K + k0 + akA0];
        ra1 = *(const float4*)&A[(size_t)(m0 + amA1) * K + k0 + akA1];
        rb0 = *(const float4*)&B[(size_t)(k0 + bkB0) * N + n0 + bnB0];
        rb1 = *(const float4*)&B[(size_t)(k0 + bkB1) * N + n0 + bnB1];
        uint4 u;
        u.x=f2tf(ra0.x); u.y=f2tf(ra0.y); u.z=f2tf(ra0.z); u.w=f2tf(ra0.w);
        *(uint4*)&As[0][amA0][akA0] = u;
        u.x=f2tf(ra1.x); u.y=f2tf(ra1.y); u.z=f2tf(ra1.z); u.w=f2tf(ra1.w);
        *(uint4*)&As[0][amA1][akA1] = u;
        u.x=f2tf(rb0.x); u.y=f2tf(rb0.y); u.z=f2tf(rb0.z); u.w=f2tf(rb0.w);
        *(uint4*)&Bs[0][bkB0][bnB0] = u;
        u.x=f2tf(rb1.x); u.y=f2tf(rb1.y); u.z=f2tf(rb1.z); u.w=f2tf(rb1.w);
        *(uint4*)&Bs[0][bkB1][bnB1] = u;
    }
    __syncthreads();

    for (int t = 0; t < T; t++) {
        // issue next-tile global loads early
        if (t + 1 < T) {
            const int k0 = (t + 1) << 4;
            ra0 = *(const float4*)&A[(size_t)(m0 + amA0) * K + k0 + akA0];
            ra1 = *(const float4*)&A[(size_t)(m0 + amA1) * K + k0 + akA1];
            rb0 = *(const float4*)&B[(size_t)(k0 + bkB0) * N + n0 + bnB0];
            rb1 = *(const float4*)&B[(size_t)(k0 + bkB1) * N + n0 + bnB1];
        }

        const int buf = t & 1;
#pragma unroll
        for (int kb = 0; kb < 16; kb += 8) {
            uint32_t af[4][4], bf[4][2];
#pragma unroll
            for (int mi = 0; mi < 4; mi++) {
                int r = wm + mi * 16 + g;
                af[mi][0] = As[buf][r    ][kb + t3];
                af[mi][1] = As[buf][r + 8][kb + t3];
                af[mi][2] = As[buf][r    ][kb + t3 + 4];
                af[mi][3] = As[buf][r + 8][kb + t3 + 4];
            }
#pragma unroll
            for (int ni = 0; ni < 4; ni++) {
                int c = wn + ni * 8 + g;
                bf[ni][0] = Bs[buf][kb + t3    ][c];
                bf[ni][1] = Bs[buf][kb + t3 + 4][c];
            }
#pragma unroll
            for (int mi = 0; mi < 4; mi++)
#pragma unroll
                for (int ni = 0; ni < 4; ni++)
                    mma_tf32(acc[mi][ni], af[mi], bf[ni]);
        }

        if (t + 1 < T) {
            const int nb = (t + 1) & 1;
            uint4 u;
            u.x=f2tf(ra0.x); u.y=f2tf(ra0.y); u.z=f2tf(ra0.z); u.w=f2tf(ra0.w);
            *(uint4*)&As[nb][amA0][akA0] = u;
            u.x=f2tf(ra1.x); u.y=f2tf(ra1.y); u.z=f2tf(ra1.z); u.w=f2tf(ra1.w);
            *(uint4*)&As[nb][amA1][akA1] = u;
            u.x=f2tf(rb0.x); u.y=f2tf(rb0.y); u.z=f2tf(rb0.z); u.w=f2tf(rb0.w);
            *(uint4*)&Bs[nb][bkB0][bnB0] = u;
            u.x=f2tf(rb1.x); u.y=f2tf(rb1.y); u.z=f2tf(rb1.z); u.w=f2tf(rb1.w);
            *(uint4*)&Bs[nb][bkB1][bnB1] = u;
            __syncthreads();
        }
    }

    // Epilogue: c0,c1 at (row, 2*t3 + {0,1}); c2,c3 at (row+8, same cols)
#pragma unroll
    for (int mi = 0; mi < 4; mi++) {
#pragma unroll
        for (int rr = 0; rr < 2; rr++) {
            int row = m0 + wm + mi * 16 + g + rr * 8;
#pragma unroll
            for (int ni = 0; ni < 4; ni++) {
                int col = n0 + wn + ni * 8 + 2 * t3;
                float v0 = acc[mi][ni][rr * 2 + 0];
                float v1 = acc[mi][ni][rr * 2 + 1];
                if (EPI >= 1) { v0 += bias[col]; v1 += bias[col + 1]; }
                if (EPI == 1) {
                    const float* Rp = res + (size_t)row * N + col;
                    v0 += Rp[0]; v1 += Rp[1];
                }
                if (EPI == 2) {
                    v0 = 0.5f * v0 * (1.0f + erff(v0 * 0.70710678118654752f));
                    v1 = 0.5f * v1 * (1.0f + erff(v1 * 0.70710678118654752f));
                }
                *(float2*)&C[(size_t)row * N + col] = make_float2(v0, v1);
            }
        }
    }
}

// ---------------------------------------------------------------------------
// Flash-style attention.  grid = (SEQ/64, NH, BATCH), 256 threads.
// logits = (q.k) * D^0.25 (reference divides by sqrt(scale), scale=D^-0.5)
// ---------------------------------------------------------------------------
__global__ __launch_bounds__(256, 1) void attn_kernel(const float* __restrict__ qkv,
                                                      float* __restrict__ out)
{
    __shared__ float Qs[64][64];
    __shared__ float Ks[64][64];   // reused as P after S is computed
    __shared__ float Vs[64][64];

    int qb = blockIdx.x;
    int h  = blockIdx.y;
    int b  = blockIdx.z;
    int tid = threadIdx.x;
    int tx = tid & 15;
    int ty = tid >> 4;

    const float SCL = 2.8284271247461903f;  // 64^0.25
    const float* base = qkv + (size_t)b * SEQ * QKV_N + h * HD;

    for (int idx = tid; idx < 64 * 64; idx += 256) {
        int r = idx >> 6, d = idx & 63;
        Qs[r][d] = base[(size_t)(qb * 64 + r) * QKV_N + d] * SCL;
    }

    float m_run[4], l_run[4];
    float o_acc[4][4];
#pragma unroll
    for (int i = 0; i < 4; i++) {
        m_run[i] = -1e30f; l_run[i] = 0.f;
#pragma unroll
        for (int j = 0; j < 4; j++) o_acc[i][j] = 0.f;
    }

    for (int kt = 0; kt < SEQ / 64; kt++) {
        __syncthreads();
        for (int idx = tid; idx < 64 * 64; idx += 256) {
            int r = idx >> 6, d = idx & 63;
            int sw = ((r >> 2) & 7) << 2;
            Ks[r][d ^ sw] = base[EMB     + (size_t)(kt * 64 + r) * QKV_N + d];
            Vs[r][d]      = base[2 * EMB + (size_t)(kt * 64 + r) * QKV_N + d];
        }
        __syncthreads();

        float s[4][4];
#pragma unroll
        for (int i = 0; i < 4; i++)
#pragma unroll
            for (int j = 0; j < 4; j++) s[i][j] = 0.f;

        for (int d = 0; d < 64; d++) {
            float qf[4], kf[4];
#pragma unroll
            for (int i = 0; i < 4; i++) qf[i] = Qs[ty * 4 + i][d];
#pragma unroll
            for (int j = 0; j < 4; j++) {
                int kr = tx * 4 + j;
                kf[j] = Ks[kr][d ^ (((kr >> 2) & 7) << 2)];
            }
#pragma unroll
            for (int i = 0; i < 4; i++)
#pragma unroll
                for (int j = 0; j < 4; j++) s[i][j] += qf[i] * kf[j];
        }

#pragma unroll
        for (int i = 0; i < 4; i++) {
            float rm = fmaxf(fmaxf(s[i][0], s[i][1]), fmaxf(s[i][2], s[i][3]));
#pragma unroll
            for (int o = 1; o < 16; o <<= 1)
                rm = fmaxf(rm, __shfl_xor_sync(0xffffffffu, rm, o));
            float mnew = fmaxf(m_run[i], rm);
            float corr = __expf(m_run[i] - mnew);
            float rs = 0.f;
#pragma unroll
            for (int j = 0; j < 4; j++) {
                s[i][j] = __expf(s[i][j] - mnew);
                rs += s[i][j];
            }
#pragma unroll
            for (int o = 1; o < 16; o <<= 1)
                rs += __shfl_xor_sync(0xffffffffu, rs, o);
            l_run[i] = l_run[i] * corr + rs;
            m_run[i] = mnew;
#pragma unroll
            for (int j = 0; j < 4; j++) o_acc[i][j] *= corr;
        }

        __syncthreads();
#pragma unroll
        for (int i = 0; i < 4; i++)
#pragma unroll
            for (int j = 0; j < 4; j++) Ks[ty * 4 + i][tx * 4 + j] = s[i][j];
        __syncthreads();

        for (int kk = 0; kk < 64; kk++) {
            float pf[4], vf[4];
#pragma unroll
            for (int i = 0; i < 4; i++) pf[i] = Ks[ty * 4 + i][kk];
#pragma unroll
            for (int j = 0; j < 4; j++) vf[j] = Vs[kk][tx * 4 + j];
#pragma unroll
            for (int i = 0; i < 4; i++)
#pragma unroll
                for (int j = 0; j < 4; j++) o_acc[i][j] += pf[i] * vf[j];
        }
    }

#pragma unroll
    for (int i = 0; i < 4; i++) {
        float inv = 1.0f / l_run[i];
        int qrow = qb * 64 + ty * 4 + i;
        float* op = out + (size_t)(b * SEQ + qrow) * EMB + h * HD + tx * 4;
#pragma unroll
        for (int j = 0; j < 4; j++) op[j] = o_acc[i][j] * inv;
    }
}

// ---------------------------------------------------------------------------
// Launch
// ---------------------------------------------------------------------------
extern "C" void kernel_launch(void* const* d_in, const int* in_sizes, int n_in,
                              void* d_out, int out_size)
{
    const float* x     = (const float*)d_in[0];
    const float* w_qkv = (const float*)d_in[1];
    const float* w_out = (const float*)d_in[2];
    const float* b_out = (const float*)d_in[3];
    const float* ln1_g = (const float*)d_in[4];
    const float* ln1_b = (const float*)d_in[5];
    const float* ln2_g = (const float*)d_in[6];
    const float* ln2_b = (const float*)d_in[7];
    const float* w1    = (const float*)d_in[8];
    const float* b1    = (const float*)d_in[9];
    const float* w2    = (const float*)d_in[10];
    const float* b2    = (const float*)d_in[11];
    float* out = (float*)d_out;

    float *p_xn, *p_qkv, *p_att, *p_x2, *p_h;
    cudaGetSymbolAddress((void**)&p_xn,  g_xn);
    cudaGetSymbolAddress((void**)&p_qkv, g_qkv);
    cudaGetSymbolAddress((void**)&p_att, g_att);
    cudaGetSymbolAddress((void**)&p_x2,  g_x2);
    cudaGetSymbolAddress((void**)&p_h,   g_h);
    float* p_xn2 = p_xn;

    // 1. LN1
    ln_kernel<<<MTOK, 256>>>(x, ln1_g, ln1_b, p_xn);
    // 2. QKV GEMM
    sgemm_tc<0><<<dim3(QKV_N / 128, MTOK / 128), 256>>>(p_xn, w_qkv, p_qkv,
                                                        nullptr, nullptr,
                                                        MTOK, QKV_N, EMB);
    // 3. Attention
    attn_kernel<<<dim3(SEQ / 64, NH, BATCH), 256>>>(p_qkv, p_att);
    // 4. Output projection + bias + residual(x)
    sgemm_tc<1><<<dim3(EMB / 128, MTOK / 128), 256>>>(p_att, w_out, p_x2,
                                                      b_out, x,
                                                      MTOK, EMB, EMB);
    // 5. LN2
    ln_kernel<<<MTOK, 256>>>(p_x2, ln2_g, ln2_b, p_xn2);
    // 6. FFN1 + bias + exact GELU
    sgemm_tc<2><<<dim3(FFD / 128, MTOK / 128), 256>>>(p_xn2, w1, p_h,
                                                      b1, nullptr,
                                                      MTOK, FFD, EMB);
    // 7. FFN2 + bias + residual(x2) -> out
    sgemm_tc<1><<<dim3(EMB / 128, MTOK / 128), 256>>>(p_h, w2, out,
                                                      b2, p_x2,
                                                      MTOK, EMB, FFD);
}

// round 5
// speedup vs baseline: 3.3023x; 1.8786x over previous
#include <cuda_runtime.h>
#include <math.h>
#include <stdint.h>

// Problem constants
#define BATCH 2
#define SEQ   2048
#define EMB   1024
#define NH    16
#define HD    64
#define FFD   4096
#define MTOK  (BATCH*SEQ)     // 4096
#define QKV_N (3*EMB)         // 3072
#define LN_EPS 1e-5f

// Scratch (device globals; allocations are forbidden in kernel_launch).
__device__ float g_xn [MTOK*EMB];     // LN1 out; reused as LN2 out
__device__ float g_qkv[MTOK*QKV_N];
__device__ float g_att[MTOK*EMB];
__device__ float g_x2 [MTOK*EMB];
__device__ float g_h  [MTOK*FFD];

// ---------------------------------------------------------------------------
// LayerNorm: one block per row of EMB=1024, 256 threads, 4 elems/thread
// ---------------------------------------------------------------------------
__global__ __launch_bounds__(256) void ln_kernel(const float* __restrict__ x,
                                                 const float* __restrict__ g,
                                                 const float* __restrict__ b,
                                                 float* __restrict__ out)
{
    int row = blockIdx.x;
    const float* xr = x + (size_t)row * EMB;
    float v[4];
    float sum = 0.f, sq = 0.f;
#pragma unroll
    for (int i = 0; i < 4; i++) {
        v[i] = xr[threadIdx.x + i * 256];
        sum += v[i];
        sq  += v[i] * v[i];
    }
#pragma unroll
    for (int o = 16; o > 0; o >>= 1) {
        sum += __shfl_xor_sync(0xffffffffu, sum, o);
        sq  += __shfl_xor_sync(0xffffffffu, sq,  o);
    }
    __shared__ float s1[8], s2[8];
    int w = threadIdx.x >> 5, l = threadIdx.x & 31;
    if (l == 0) { s1[w] = sum; s2[w] = sq; }
    __syncthreads();
    sum = 0.f; sq = 0.f;
#pragma unroll
    for (int i = 0; i < 8; i++) { sum += s1[i]; sq += s2[i]; }
    float mu  = sum * (1.0f / EMB);
    float var = sq * (1.0f / EMB) - mu * mu;
    float inv = rsqrtf(var + LN_EPS);
    float* orow = out + (size_t)row * EMB;
#pragma unroll
    for (int i = 0; i < 4; i++) {
        int c = threadIdx.x + i * 256;
        orow[c] = (v[i] - mu) * inv * g[c] + b[c];
    }
}

// ---------------------------------------------------------------------------
// tf32 mma helpers
// ---------------------------------------------------------------------------
__device__ __forceinline__ uint32_t f2tf(float f)
{
    uint32_t r;
    asm("cvt.rna.tf32.f32 %0, %1;" : "=r"(r) : "f"(f));
    return r;
}

__device__ __forceinline__ void mma_tf32(float* d, const uint32_t* a, const uint32_t* b)
{
    asm volatile(
        "mma.sync.aligned.m16n8k8.row.col.f32.tf32.tf32.f32 "
        "{%0,%1,%2,%3}, {%4,%5,%6,%7}, {%8,%9}, {%0,%1,%2,%3};\n"
        : "+f"(d[0]), "+f"(d[1]), "+f"(d[2]), "+f"(d[3])
        : "r"(a[0]), "r"(a[1]), "r"(a[2]), "r"(a[3]), "r"(b[0]), "r"(b[1]));
}

// ---------------------------------------------------------------------------
// tf32 tensor-core GEMM: 128x128x16 CTA tile, 8 warps (2x4), warp tile 64x32,
// double-buffered smem, fp32 accumulate.  A[M,K], B[K,N] row-major.
// EPI: 0 none, 1 +bias+res, 2 +bias+GELU(exact)
// ---------------------------------------------------------------------------
#define SA 20    // As row stride (uint32): banks (20*g + t3) conflict-free
#define SB 136   // Bs row stride (uint32): banks (8*t3 + g) conflict-free

template <int EPI>
__global__ __launch_bounds__(256) void sgemm_tc(const float* __restrict__ A,
                                                const float* __restrict__ B,
                                                float* __restrict__ C,
                                                const float* __restrict__ bias,
                                                const float* __restrict__ res,
                                                int M, int N, int K)
{
    __shared__ uint32_t As[2][128][SA];
    __shared__ uint32_t Bs[2][16][SB];

    const int tid = threadIdx.x;
    const int m0 = blockIdx.y * 128;
    const int n0 = blockIdx.x * 128;

    const int warpId = tid >> 5;
    const int lane   = tid & 31;
    const int wm = (warpId & 1) * 64;
    const int wn = (warpId >> 1) * 32;
    const int g  = lane >> 2;
    const int t3 = lane & 3;

    const int amA0 = (tid) >> 2,        akA0 = ((tid) & 3) << 2;
    const int amA1 = (tid + 256) >> 2,  akA1 = ((tid + 256) & 3) << 2;
    const int bkB0 = (tid) >> 5,        bnB0 = ((tid) & 31) << 2;
    const int bkB1 = (tid + 256) >> 5,  bnB1 = ((tid + 256) & 31) << 2;

    float acc[4][4][4];
#pragma unroll
    for (int i = 0; i < 4; i++)
#pragma unroll
        for (int j = 0; j < 4; j++)
#pragma unroll
            for (int c = 0; c < 4; c++) acc[i][j][c] = 0.f;

    const int T = K >> 4;
    float4 ra0, ra1, rb0, rb1;

    {
        ra0 = *(const float4*)&A[(size_t)(m0 + amA0) * K + akA0];
        ra1 = *(const float4*)&A[(size_t)(m0 + amA1) * K + akA1];
        rb0 = *(const float4*)&B[(size_t)(bkB0) * N + n0 + bnB0];
        rb1 = *(const float4*)&B[(size_t)(bkB1) * N + n0 + bnB1];
        uint4 u;
        u.x=f2tf(ra0.x); u.y=f2tf(ra0.y); u.z=f2tf(ra0.z); u.w=f2tf(ra0.w);
        *(uint4*)&As[0][amA0][akA0] = u;
        u.x=f2tf(ra1.x); u.y=f2tf(ra1.y); u.z=f2tf(ra1.z); u.w=f2tf(ra1.w);
        *(uint4*)&As[0][amA1][akA1] = u;
        u.x=f2tf(rb0.x); u.y=f2tf(rb0.y); u.z=f2tf(rb0.z); u.w=f2tf(rb0.w);
        *(uint4*)&Bs[0][bkB0][bnB0] = u;
        u.x=f2tf(rb1.x); u.y=f2tf(rb1.y); u.z=f2tf(rb1.z); u.w=f2tf(rb1.w);
        *(uint4*)&Bs[0][bkB1][bnB1] = u;
    }
    __syncthreads();

    for (int t = 0; t < T; t++) {
        if (t + 1 < T) {
            const int k0 = (t + 1) << 4;
            ra0 = *(const float4*)&A[(size_t)(m0 + amA0) * K + k0 + akA0];
            ra1 = *(const float4*)&A[(size_t)(m0 + amA1) * K + k0 + akA1];
            rb0 = *(const float4*)&B[(size_t)(k0 + bkB0) * N + n0 + bnB0];
            rb1 = *(const float4*)&B[(size_t)(k0 + bkB1) * N + n0 + bnB1];
        }

        const int buf = t & 1;
#pragma unroll
        for (int kb = 0; kb < 16; kb += 8) {
            uint32_t af[4][4], bf[4][2];
#pragma unroll
            for (int mi = 0; mi < 4; mi++) {
                int r = wm + mi * 16 + g;
                af[mi][0] = As[buf][r    ][kb + t3];
                af[mi][1] = As[buf][r + 8][kb + t3];
                af[mi][2] = As[buf][r    ][kb + t3 + 4];
                af[mi][3] = As[buf][r + 8][kb + t3 + 4];
            }
#pragma unroll
            for (int ni = 0; ni < 4; ni++) {
                int c = wn + ni * 8 + g;
                bf[ni][0] = Bs[buf][kb + t3    ][c];
                bf[ni][1] = Bs[buf][kb + t3 + 4][c];
            }
#pragma unroll
            for (int mi = 0; mi < 4; mi++)
#pragma unroll
                for (int ni = 0; ni < 4; ni++)
                    mma_tf32(acc[mi][ni], af[mi], bf[ni]);
        }

        if (t + 1 < T) {
            const int nb = (t + 1) & 1;
            uint4 u;
            u.x=f2tf(ra0.x); u.y=f2tf(ra0.y); u.z=f2tf(ra0.z); u.w=f2tf(ra0.w);
            *(uint4*)&As[nb][amA0][akA0] = u;
            u.x=f2tf(ra1.x); u.y=f2tf(ra1.y); u.z=f2tf(ra1.z); u.w=f2tf(ra1.w);
            *(uint4*)&As[nb][amA1][akA1] = u;
            u.x=f2tf(rb0.x); u.y=f2tf(rb0.y); u.z=f2tf(rb0.z); u.w=f2tf(rb0.w);
            *(uint4*)&Bs[nb][bkB0][bnB0] = u;
            u.x=f2tf(rb1.x); u.y=f2tf(rb1.y); u.z=f2tf(rb1.z); u.w=f2tf(rb1.w);
            *(uint4*)&Bs[nb][bkB1][bnB1] = u;
            __syncthreads();
        }
    }

#pragma unroll
    for (int mi = 0; mi < 4; mi++) {
#pragma unroll
        for (int rr = 0; rr < 2; rr++) {
            int row = m0 + wm + mi * 16 + g + rr * 8;
#pragma unroll
            for (int ni = 0; ni < 4; ni++) {
                int col = n0 + wn + ni * 8 + 2 * t3;
                float v0 = acc[mi][ni][rr * 2 + 0];
                float v1 = acc[mi][ni][rr * 2 + 1];
                if (EPI >= 1) { v0 += bias[col]; v1 += bias[col + 1]; }
                if (EPI == 1) {
                    const float* Rp = res + (size_t)row * N + col;
                    v0 += Rp[0]; v1 += Rp[1];
                }
                if (EPI == 2) {
                    v0 = 0.5f * v0 * (1.0f + erff(v0 * 0.70710678118654752f));
                    v1 = 0.5f * v1 * (1.0f + erff(v1 * 0.70710678118654752f));
                }
                *(float2*)&C[(size_t)row * N + col] = make_float2(v0, v1);
            }
        }
    }
}

// ---------------------------------------------------------------------------
// Tensor-core flash attention. grid=(SEQ/64, NH, BATCH), 128 threads (4 warps).
// Each warp owns 16 q-rows. Q kept as tf32 A-fragments in registers.
// S = Q.K^T via m16n8k8; online softmax on accumulator layout; P written
// (tf32) into the Ks buffer; O += P.V via m16n8k8.
// logits scaled by D^0.25 (reference: (q.k)/sqrt(scale), scale=D^-0.5).
// ---------------------------------------------------------------------------
__global__ __launch_bounds__(128) void attn_tc(const float* __restrict__ qkv,
                                               float* __restrict__ out)
{
    __shared__ uint32_t Ks[64][68];   // K tile (tf32), then reused as P
    __shared__ uint32_t Vs[64][72];   // V tile (tf32)

    const int qb = blockIdx.x;
    const int h  = blockIdx.y;
    const int b  = blockIdx.z;
    const int tid  = threadIdx.x;
    const int w    = tid >> 5;
    const int lane = tid & 31;
    const int g  = lane >> 2;
    const int t3 = lane & 3;

    const float SCL = 2.8284271247461903f;  // 64^0.25
    const float* base = qkv + (size_t)b * SEQ * QKV_N + h * HD;

    const int qr0 = qb * 64 + w * 16 + g;           // this thread's row (and +8)
    const float* q0 = base + (size_t)qr0 * QKV_N;
    const float* q8 = q0 + (size_t)8 * QKV_N;

    // Q A-fragments (scaled, tf32), one per 8-wide d-chunk
    uint32_t qf[8][4];
#pragma unroll
    for (int kb = 0; kb < 8; kb++) {
        qf[kb][0] = f2tf(q0[kb * 8 + t3]     * SCL);
        qf[kb][1] = f2tf(q8[kb * 8 + t3]     * SCL);
        qf[kb][2] = f2tf(q0[kb * 8 + t3 + 4] * SCL);
        qf[kb][3] = f2tf(q8[kb * 8 + t3 + 4] * SCL);
    }

    float oacc[8][4];
#pragma unroll
    for (int i = 0; i < 8; i++)
#pragma unroll
        for (int c = 0; c < 4; c++) oacc[i][c] = 0.f;
    float m0 = -1e30f, m1 = -1e30f, l0 = 0.f, l1 = 0.f;

    for (int kt = 0; kt < SEQ / 64; kt++) {
        __syncthreads();   // previous tile's P/V reads complete
        // Load K,V 64x64 tiles as tf32 (float4-coalesced)
        for (int i = tid; i < 64 * 16; i += 128) {
            int r = i >> 4, c = (i & 15) << 2;
            const float* kp = base + EMB + (size_t)(kt * 64 + r) * QKV_N + c;
            float4 k4 = *(const float4*)kp;
            float4 v4 = *(const float4*)(kp + EMB);
            uint4 ku, vu;
            ku.x=f2tf(k4.x); ku.y=f2tf(k4.y); ku.z=f2tf(k4.z); ku.w=f2tf(k4.w);
            vu.x=f2tf(v4.x); vu.y=f2tf(v4.y); vu.z=f2tf(v4.z); vu.w=f2tf(v4.w);
            *(uint4*)&Ks[r][c] = ku;
            *(uint4*)&Vs[r][c] = vu;
        }
        __syncthreads();

        // S = Q.K^T  (warp: 16 x 64)
        float sacc[8][4];
#pragma unroll
        for (int i = 0; i < 8; i++)
#pragma unroll
            for (int c = 0; c < 4; c++) sacc[i][c] = 0.f;

#pragma unroll
        for (int kb = 0; kb < 8; kb++) {
#pragma unroll
            for (int ni = 0; ni < 8; ni++) {
                uint32_t bf[2];
                bf[0] = Ks[ni * 8 + g][kb * 8 + t3];
                bf[1] = Ks[ni * 8 + g][kb * 8 + t3 + 4];
                mma_tf32(sacc[ni], qf[kb], bf);
            }
        }

        // Online softmax: rows g (c0,c1) and g+8 (c2,c3); 4-lane shfl reduce
        float rm0 = -1e30f, rm1 = -1e30f;
#pragma unroll
        for (int ni = 0; ni < 8; ni++) {
            rm0 = fmaxf(rm0, fmaxf(sacc[ni][0], sacc[ni][1]));
            rm1 = fmaxf(rm1, fmaxf(sacc[ni][2], sacc[ni][3]));
        }
        rm0 = fmaxf(rm0, __shfl_xor_sync(0xffffffffu, rm0, 1));
        rm0 = fmaxf(rm0, __shfl_xor_sync(0xffffffffu, rm0, 2));
        rm1 = fmaxf(rm1, __shfl_xor_sync(0xffffffffu, rm1, 1));
        rm1 = fmaxf(rm1, __shfl_xor_sync(0xffffffffu, rm1, 2));
        float mn0 = fmaxf(m0, rm0), mn1 = fmaxf(m1, rm1);
        float cr0 = __expf(m0 - mn0), cr1 = __expf(m1 - mn1);
        float rs0 = 0.f, rs1 = 0.f;
#pragma unroll
        for (int ni = 0; ni < 8; ni++) {
            sacc[ni][0] = __expf(sacc[ni][0] - mn0);
            sacc[ni][1] = __expf(sacc[ni][1] - mn0);
            sacc[ni][2] = __expf(sacc[ni][2] - mn1);
            sacc[ni][3] = __expf(sacc[ni][3] - mn1);
            rs0 += sacc[ni][0] + sacc[ni][1];
            rs1 += sacc[ni][2] + sacc[ni][3];
        }
        rs0 += __shfl_xor_sync(0xffffffffu, rs0, 1);
        rs0 += __shfl_xor_sync(0xffffffffu, rs0, 2);
        rs1 += __shfl_xor_sync(0xffffffffu, rs1, 1);
        rs1 += __shfl_xor_sync(0xffffffffu, rs1, 2);
        l0 = l0 * cr0 + rs0;  m0 = mn0;
        l1 = l1 * cr1 + rs1;  m1 = mn1;
#pragma unroll
        for (int di = 0; di < 8; di++) {
            oacc[di][0] *= cr0; oacc[di][1] *= cr0;
            oacc[di][2] *= cr1; oacc[di][3] *= cr1;
        }

        __syncthreads();   // all warps finished S-mma reads of Ks
        // Write P (tf32) into Ks rows [w*16, w*16+16)
        const int pr = w * 16 + g;
#pragma unroll
        for (int ni = 0; ni < 8; ni++) {
            Ks[pr    ][ni * 8 + 2 * t3]     = f2tf(sacc[ni][0]);
            Ks[pr    ][ni * 8 + 2 * t3 + 1] = f2tf(sacc[ni][1]);
            Ks[pr + 8][ni * 8 + 2 * t3]     = f2tf(sacc[ni][2]);
            Ks[pr + 8][ni * 8 + 2 * t3 + 1] = f2tf(sacc[ni][3]);
        }
        __syncwarp();

        // O += P.V
#pragma unroll
        for (int kc = 0; kc < 8; kc++) {
            uint32_t pa[4];
            pa[0] = Ks[pr    ][kc * 8 + t3];
            pa[1] = Ks[pr + 8][kc * 8 + t3];
            pa[2] = Ks[pr    ][kc * 8 + t3 + 4];
            pa[3] = Ks[pr + 8][kc * 8 + t3 + 4];
#pragma unroll
            for (int di = 0; di < 8; di++) {
                uint32_t bf[2];
                bf[0] = Vs[kc * 8 + t3    ][di * 8 + g];
                bf[1] = Vs[kc * 8 + t3 + 4][di * 8 + g];
                mma_tf32(oacc[di], pa, bf);
            }
        }
    }

    // Normalize and store: out[b, q, h*64 + d]
    float inv0 = 1.0f / l0, inv1 = 1.0f / l1;
    float* o0 = out + (size_t)(b * SEQ + qr0) * EMB + h * HD;
    float* o8 = o0 + (size_t)8 * EMB;
#pragma unroll
    for (int di = 0; di < 8; di++) {
        int col = di * 8 + 2 * t3;
        *(float2*)&o0[col] = make_float2(oacc[di][0] * inv0, oacc[di][1] * inv0);
        *(float2*)&o8[col] = make_float2(oacc[di][2] * inv1, oacc[di][3] * inv1);
    }
}

// ---------------------------------------------------------------------------
// Launch
// ---------------------------------------------------------------------------
extern "C" void kernel_launch(void* const* d_in, const int* in_sizes, int n_in,
                              void* d_out, int out_size)
{
    const float* x     = (const float*)d_in[0];
    const float* w_qkv = (const float*)d_in[1];
    const float* w_out = (const float*)d_in[2];
    const float* b_out = (const float*)d_in[3];
    const float* ln1_g = (const float*)d_in[4];
    const float* ln1_b = (const float*)d_in[5];
    const float* ln2_g = (const float*)d_in[6];
    const float* ln2_b = (const float*)d_in[7];
    const float* w1    = (const float*)d_in[8];
    const float* b1    = (const float*)d_in[9];
    const float* w2    = (const float*)d_in[10];
    const float* b2    = (const float*)d_in[11];
    float* out = (float*)d_out;

    float *p_xn, *p_qkv, *p_att, *p_x2, *p_h;
    cudaGetSymbolAddress((void**)&p_xn,  g_xn);
    cudaGetSymbolAddress((void**)&p_qkv, g_qkv);
    cudaGetSymbolAddress((void**)&p_att, g_att);
    cudaGetSymbolAddress((void**)&p_x2,  g_x2);
    cudaGetSymbolAddress((void**)&p_h,   g_h);
    float* p_xn2 = p_xn;

    // 1. LN1
    ln_kernel<<<MTOK, 256>>>(x, ln1_g, ln1_b, p_xn);
    // 2. QKV GEMM
    sgemm_tc<0><<<dim3(QKV_N / 128, MTOK / 128), 256>>>(p_xn, w_qkv, p_qkv,
                                                        nullptr, nullptr,
                                                        MTOK, QKV_N, EMB);
    // 3. Attention (tensor-core)
    attn_tc<<<dim3(SEQ / 64, NH, BATCH), 128>>>(p_qkv, p_att);
    // 4. Output projection + bias + residual(x)
    sgemm_tc<1><<<dim3(EMB / 128, MTOK / 128), 256>>>(p_att, w_out, p_x2,
                                                      b_out, x,
                                                      MTOK, EMB, EMB);
    // 5. LN2
    ln_kernel<<<MTOK, 256>>>(p_x2, ln2_g, ln2_b, p_xn2);
    // 6. FFN1 + bias + exact GELU
    sgemm_tc<2><<<dim3(FFD / 128, MTOK / 128), 256>>>(p_xn2, w1, p_h,
                                                      b1, nullptr,
                                                      MTOK, FFD, EMB);
    // 7. FFN2 + bias + residual(x2) -> out
    sgemm_tc<1><<<dim3(EMB / 128, MTOK / 128), 256>>>(p_h, w2, out,
                                                      b2, p_x2,
                                                      MTOK, EMB, FFD);
}

// round 6
// speedup vs baseline: 4.0344x; 1.2217x over previous
#include <cuda_runtime.h>
#include <cuda_fp16.h>
#include <math.h>
#include <stdint.h>

// Problem constants
#define BATCH 2
#define SEQ   2048
#define EMB   1024
#define NH    16
#define HD    64
#define FFD   4096
#define MTOK  (BATCH*SEQ)     // 4096
#define QKV_N (3*EMB)         // 3072
#define LN_EPS 1e-5f

// Scratch (device globals; allocations are forbidden in kernel_launch).
__device__ float g_xn [MTOK*EMB];     // LN1 out; reused as LN2 out
__device__ float g_qkv[MTOK*QKV_N];
__device__ float g_att[MTOK*EMB];
__device__ float g_x2 [MTOK*EMB];
__device__ float g_h  [MTOK*FFD];

// ---------------------------------------------------------------------------
// LayerNorm: one block per row of EMB=1024, 256 threads, 4 elems/thread
// ---------------------------------------------------------------------------
__global__ __launch_bounds__(256) void ln_kernel(const float* __restrict__ x,
                                                 const float* __restrict__ g,
                                                 const float* __restrict__ b,
                                                 float* __restrict__ out)
{
    int row = blockIdx.x;
    const float* xr = x + (size_t)row * EMB;
    float v[4];
    float sum = 0.f, sq = 0.f;
#pragma unroll
    for (int i = 0; i < 4; i++) {
        v[i] = xr[threadIdx.x + i * 256];
        sum += v[i];
        sq  += v[i] * v[i];
    }
#pragma unroll
    for (int o = 16; o > 0; o >>= 1) {
        sum += __shfl_xor_sync(0xffffffffu, sum, o);
        sq  += __shfl_xor_sync(0xffffffffu, sq,  o);
    }
    __shared__ float s1[8], s2[8];
    int w = threadIdx.x >> 5, l = threadIdx.x & 31;
    if (l == 0) { s1[w] = sum; s2[w] = sq; }
    __syncthreads();
    sum = 0.f; sq = 0.f;
#pragma unroll
    for (int i = 0; i < 8; i++) { sum += s1[i]; sq += s2[i]; }
    float mu  = sum * (1.0f / EMB);
    float var = sq * (1.0f / EMB) - mu * mu;
    float inv = rsqrtf(var + LN_EPS);
    float* orow = out + (size_t)row * EMB;
#pragma unroll
    for (int i = 0; i < 4; i++) {
        int c = threadIdx.x + i * 256;
        orow[c] = (v[i] - mu) * inv * g[c] + b[c];
    }
}

// ---------------------------------------------------------------------------
// mma helpers
// ---------------------------------------------------------------------------
__device__ __forceinline__ uint32_t f2tf(float f)
{
    uint32_t r;
    asm("cvt.rna.tf32.f32 %0, %1;" : "=r"(r) : "f"(f));
    return r;
}

// pack two fp32 into fp16x2 word: low half = lo, high half = hi
__device__ __forceinline__ uint32_t pack2h(float lo, float hi)
{
    uint32_t r;
    asm("cvt.rn.f16x2.f32 %0, %1, %2;" : "=r"(r) : "f"(hi), "f"(lo));
    return r;
}

__device__ __forceinline__ void mma_tf32(float* d, const uint32_t* a, const uint32_t* b)
{
    asm volatile(
        "mma.sync.aligned.m16n8k8.row.col.f32.tf32.tf32.f32 "
        "{%0,%1,%2,%3}, {%4,%5,%6,%7}, {%8,%9}, {%0,%1,%2,%3};\n"
        : "+f"(d[0]), "+f"(d[1]), "+f"(d[2]), "+f"(d[3])
        : "r"(a[0]), "r"(a[1]), "r"(a[2]), "r"(a[3]), "r"(b[0]), "r"(b[1]));
}

__device__ __forceinline__ void mma_f16(float* d, const uint32_t* a, const uint32_t* b)
{
    asm volatile(
        "mma.sync.aligned.m16n8k16.row.col.f32.f16.f16.f32 "
        "{%0,%1,%2,%3}, {%4,%5,%6,%7}, {%8,%9}, {%0,%1,%2,%3};\n"
        : "+f"(d[0]), "+f"(d[1]), "+f"(d[2]), "+f"(d[3])
        : "r"(a[0]), "r"(a[1]), "r"(a[2]), "r"(a[3]), "r"(b[0]), "r"(b[1]));
}

// ---------------------------------------------------------------------------
// fp16 tensor-core GEMM: 128x128x16 CTA tile, 8 warps (2x4), warp tile 64x32,
// mma.m16n8k16.f16 with fp32 accumulate, double-buffered smem.
// smem words are fp16x2 packed along K: As[m][kw] = (A[m][2kw],A[m][2kw+1]),
// Bs[kw][n] = (B[2kw][n],B[2kw+1][n]).  Fragment-load indices in word units
// are identical to the validated tf32 kernel (conflict-free banks).
// A[M,K], B[K,N] row-major fp32.  EPI: 0 none, 1 +bias+res, 2 +bias+GELU.
// Requires M%128==0, N%128==0, K%16==0.
// ---------------------------------------------------------------------------
#define SA 20    // As row stride (words): frag banks (20*g + t3) conflict-free
#define SB 136   // Bs row stride (words): frag banks (8*t3 + g) conflict-free

template <int EPI>
__global__ __launch_bounds__(256) void sgemm_hc(const float* __restrict__ A,
                                                const float* __restrict__ B,
                                                float* __restrict__ C,
                                                const float* __restrict__ bias,
                                                const float* __restrict__ res,
                                                int M, int N, int K)
{
    __shared__ uint32_t As[2][128][SA];   // 8 k-words per tile used
    __shared__ uint32_t Bs[2][8][SB];

    const int tid = threadIdx.x;
    const int m0 = blockIdx.y * 128;
    const int n0 = blockIdx.x * 128;

    const int warpId = tid >> 5;
    const int lane   = tid & 31;
    const int wm = (warpId & 1) * 64;
    const int wn = (warpId >> 1) * 32;
    const int g  = lane >> 2;
    const int t3 = lane & 3;

    // A fill: thread -> row tid>>1, word-chunk (tid&1)*4 (k elems 0-7 / 8-15)
    const int amA = tid >> 1;
    const int awA = (tid & 1) * 4;       // word offset in row
    // B fill: thread -> k-word tid>>5 (0..7), n chunk (tid&31)*4
    const int bkw = tid >> 5;
    const int bn4 = (tid & 31) * 4;

    float acc[4][4][4];
#pragma unroll
    for (int i = 0; i < 4; i++)
#pragma unroll
        for (int j = 0; j < 4; j++)
#pragma unroll
            for (int c = 0; c < 4; c++) acc[i][j][c] = 0.f;

    const int T = K >> 4;   // 16-wide k tiles
    float4 ra0, ra1, rb0, rb1;

    // prefetch tile 0
    {
        const float* Ap = &A[(size_t)(m0 + amA) * K + awA * 2];
        ra0 = *(const float4*)Ap;
        ra1 = *(const float4*)(Ap + 4);
        const float* Bp = &B[(size_t)(2 * bkw) * N + n0 + bn4];
        rb0 = *(const float4*)Bp;
        rb1 = *(const float4*)(Bp + N);
        uint4 u;
        u.x = pack2h(ra0.x, ra0.y); u.y = pack2h(ra0.z, ra0.w);
        u.z = pack2h(ra1.x, ra1.y); u.w = pack2h(ra1.z, ra1.w);
        *(uint4*)&As[0][amA][awA] = u;
        u.x = pack2h(rb0.x, rb1.x); u.y = pack2h(rb0.y, rb1.y);
        u.z = pack2h(rb0.z, rb1.z); u.w = pack2h(rb0.w, rb1.w);
        *(uint4*)&Bs[0][bkw][bn4] = u;
    }
    __syncthreads();

    for (int t = 0; t < T; t++) {
        if (t + 1 < T) {
            const int k0 = (t + 1) << 4;
            const float* Ap = &A[(size_t)(m0 + amA) * K + k0 + awA * 2];
            ra0 = *(const float4*)Ap;
            ra1 = *(const float4*)(Ap + 4);
            const float* Bp = &B[(size_t)(k0 + 2 * bkw) * N + n0 + bn4];
            rb0 = *(const float4*)Bp;
            rb1 = *(const float4*)(Bp + N);
        }

        const int buf = t & 1;
        uint32_t af[4][4], bf[4][2];
#pragma unroll
        for (int mi = 0; mi < 4; mi++) {
            int r = wm + mi * 16 + g;
            af[mi][0] = As[buf][r    ][t3];
            af[mi][1] = As[buf][r + 8][t3];
            af[mi][2] = As[buf][r    ][t3 + 4];
            af[mi][3] = As[buf][r + 8][t3 + 4];
        }
#pragma unroll
        for (int ni = 0; ni < 4; ni++) {
            int c = wn + ni * 8 + g;
            bf[ni][0] = Bs[buf][t3    ][c];
            bf[ni][1] = Bs[buf][t3 + 4][c];
        }
#pragma unroll
        for (int mi = 0; mi < 4; mi++)
#pragma unroll
            for (int ni = 0; ni < 4; ni++)
                mma_f16(acc[mi][ni], af[mi], bf[ni]);

        if (t + 1 < T) {
            const int nb = (t + 1) & 1;
            uint4 u;
            u.x = pack2h(ra0.x, ra0.y); u.y = pack2h(ra0.z, ra0.w);
            u.z = pack2h(ra1.x, ra1.y); u.w = pack2h(ra1.z, ra1.w);
            *(uint4*)&As[nb][amA][awA] = u;
            u.x = pack2h(rb0.x, rb1.x); u.y = pack2h(rb0.y, rb1.y);
            u.z = pack2h(rb0.z, rb1.z); u.w = pack2h(rb0.w, rb1.w);
            *(uint4*)&Bs[nb][bkw][bn4] = u;
            __syncthreads();
        }
    }

    // Epilogue: c0,c1 at (row, 2*t3 + {0,1}); c2,c3 at (row+8, same cols)
#pragma unroll
    for (int mi = 0; mi < 4; mi++) {
#pragma unroll
        for (int rr = 0; rr < 2; rr++) {
            int row = m0 + wm + mi * 16 + g + rr * 8;
#pragma unroll
            for (int ni = 0; ni < 4; ni++) {
                int col = n0 + wn + ni * 8 + 2 * t3;
                float v0 = acc[mi][ni][rr * 2 + 0];
                float v1 = acc[mi][ni][rr * 2 + 1];
                if (EPI >= 1) { v0 += bias[col]; v1 += bias[col + 1]; }
                if (EPI == 1) {
                    const float* Rp = res + (size_t)row * N + col;
                    v0 += Rp[0]; v1 += Rp[1];
                }
                if (EPI == 2) {
                    v0 = 0.5f * v0 * (1.0f + erff(v0 * 0.70710678118654752f));
                    v1 = 0.5f * v1 * (1.0f + erff(v1 * 0.70710678118654752f));
                }
                *(float2*)&C[(size_t)row * N + col] = make_float2(v0, v1);
            }
        }
    }
}

// ---------------------------------------------------------------------------
// Tensor-core flash attention (tf32). grid=(SEQ/64, NH, BATCH), 128 threads.
// ---------------------------------------------------------------------------
__global__ __launch_bounds__(128) void attn_tc(const float* __restrict__ qkv,
                                               float* __restrict__ out)
{
    __shared__ uint32_t Ks[64][68];   // K tile (tf32), then reused as P
    __shared__ uint32_t Vs[64][72];   // V tile (tf32)

    const int qb = blockIdx.x;
    const int h  = blockIdx.y;
    const int b  = blockIdx.z;
    const int tid  = threadIdx.x;
    const int w    = tid >> 5;
    const int lane = tid & 31;
    const int g  = lane >> 2;
    const int t3 = lane & 3;

    const float SCL = 2.8284271247461903f;  // 64^0.25
    const float* base = qkv + (size_t)b * SEQ * QKV_N + h * HD;

    const int qr0 = qb * 64 + w * 16 + g;
    const float* q0 = base + (size_t)qr0 * QKV_N;
    const float* q8 = q0 + (size_t)8 * QKV_N;

    uint32_t qf[8][4];
#pragma unroll
    for (int kb = 0; kb < 8; kb++) {
        qf[kb][0] = f2tf(q0[kb * 8 + t3]     * SCL);
        qf[kb][1] = f2tf(q8[kb * 8 + t3]     * SCL);
        qf[kb][2] = f2tf(q0[kb * 8 + t3 + 4] * SCL);
        qf[kb][3] = f2tf(q8[kb * 8 + t3 + 4] * SCL);
    }

    float oacc[8][4];
#pragma unroll
    for (int i = 0; i < 8; i++)
#pragma unroll
        for (int c = 0; c < 4; c++) oacc[i][c] = 0.f;
    float m0 = -1e30f, m1 = -1e30f, l0 = 0.f, l1 = 0.f;

    for (int kt = 0; kt < SEQ / 64; kt++) {
        __syncthreads();
        for (int i = tid; i < 64 * 16; i += 128) {
            int r = i >> 4, c = (i & 15) << 2;
            const float* kp = base + EMB + (size_t)(kt * 64 + r) * QKV_N + c;
            float4 k4 = *(const float4*)kp;
            float4 v4 = *(const float4*)(kp + EMB);
            uint4 ku, vu;
            ku.x=f2tf(k4.x); ku.y=f2tf(k4.y); ku.z=f2tf(k4.z); ku.w=f2tf(k4.w);
            vu.x=f2tf(v4.x); vu.y=f2tf(v4.y); vu.z=f2tf(v4.z); vu.w=f2tf(v4.w);
            *(uint4*)&Ks[r][c] = ku;
            *(uint4*)&Vs[r][c] = vu;
        }
        __syncthreads();

        float sacc[8][4];
#pragma unroll
        for (int i = 0; i < 8; i++)
#pragma unroll
            for (int c = 0; c < 4; c++) sacc[i][c] = 0.f;

#pragma unroll
        for (int kb = 0; kb < 8; kb++) {
#pragma unroll
            for (int ni = 0; ni < 8; ni++) {
                uint32_t bf[2];
                bf[0] = Ks[ni * 8 + g][kb * 8 + t3];
                bf[1] = Ks[ni * 8 + g][kb * 8 + t3 + 4];
                mma_tf32(sacc[ni], qf[kb], bf);
            }
        }

        float rm0 = -1e30f, rm1 = -1e30f;
#pragma unroll
        for (int ni = 0; ni < 8; ni++) {
            rm0 = fmaxf(rm0, fmaxf(sacc[ni][0], sacc[ni][1]));
            rm1 = fmaxf(rm1, fmaxf(sacc[ni][2], sacc[ni][3]));
        }
        rm0 = fmaxf(rm0, __shfl_xor_sync(0xffffffffu, rm0, 1));
        rm0 = fmaxf(rm0, __shfl_xor_sync(0xffffffffu, rm0, 2));
        rm1 = fmaxf(rm1, __shfl_xor_sync(0xffffffffu, rm1, 1));
        rm1 = fmaxf(rm1, __shfl_xor_sync(0xffffffffu, rm1, 2));
        float mn0 = fmaxf(m0, rm0), mn1 = fmaxf(m1, rm1);
        float cr0 = __expf(m0 - mn0), cr1 = __expf(m1 - mn1);
        float rs0 = 0.f, rs1 = 0.f;
#pragma unroll
        for (int ni = 0; ni < 8; ni++) {
            sacc[ni][0] = __expf(sacc[ni][0] - mn0);
            sacc[ni][1] = __expf(sacc[ni][1] - mn0);
            sacc[ni][2] = __expf(sacc[ni][2] - mn1);
            sacc[ni][3] = __expf(sacc[ni][3] - mn1);
            rs0 += sacc[ni][0] + sacc[ni][1];
            rs1 += sacc[ni][2] + sacc[ni][3];
        }
        rs0 += __shfl_xor_sync(0xffffffffu, rs0, 1);
        rs0 += __shfl_xor_sync(0xffffffffu, rs0, 2);
        rs1 += __shfl_xor_sync(0xffffffffu, rs1, 1);
        rs1 += __shfl_xor_sync(0xffffffffu, rs1, 2);
        l0 = l0 * cr0 + rs0;  m0 = mn0;
        l1 = l1 * cr1 + rs1;  m1 = mn1;
#pragma unroll
        for (int di = 0; di < 8; di++) {
            oacc[di][0] *= cr0; oacc[di][1] *= cr0;
            oacc[di][2] *= cr1; oacc[di][3] *= cr1;
        }

        __syncthreads();
        const int pr = w * 16 + g;
#pragma unroll
        for (int ni = 0; ni < 8; ni++) {
            Ks[pr    ][ni * 8 + 2 * t3]     = f2tf(sacc[ni][0]);
            Ks[pr    ][ni * 8 + 2 * t3 + 1] = f2tf(sacc[ni][1]);
            Ks[pr + 8][ni * 8 + 2 * t3]     = f2tf(sacc[ni][2]);
            Ks[pr + 8][ni * 8 + 2 * t3 + 1] = f2tf(sacc[ni][3]);
        }
        __syncwarp();

#pragma unroll
        for (int kc = 0; kc < 8; kc++) {
            uint32_t pa[4];
            pa[0] = Ks[pr    ][kc * 8 + t3];
            pa[1] = Ks[pr + 8][kc * 8 + t3];
            pa[2] = Ks[pr    ][kc * 8 + t3 + 4];
            pa[3] = Ks[pr + 8][kc * 8 + t3 + 4];
#pragma unroll
            for (int di = 0; di < 8; di++) {
                uint32_t bf[2];
                bf[0] = Vs[kc * 8 + t3    ][di * 8 + g];
                bf[1] = Vs[kc * 8 + t3 + 4][di * 8 + g];
                mma_tf32(oacc[di], pa, bf);
            }
        }
    }

    float inv0 = 1.0f / l0, inv1 = 1.0f / l1;
    float* o0 = out + (size_t)(b * SEQ + qr0) * EMB + h * HD;
    float* o8 = o0 + (size_t)8 * EMB;
#pragma unroll
    for (int di = 0; di < 8; di++) {
        int col = di * 8 + 2 * t3;
        *(float2*)&o0[col] = make_float2(oacc[di][0] * inv0, oacc[di][1] * inv0);
        *(float2*)&o8[col] = make_float2(oacc[di][2] * inv1, oacc[di][3] * inv1);
    }
}

// ---------------------------------------------------------------------------
// Launch
// ---------------------------------------------------------------------------
extern "C" void kernel_launch(void* const* d_in, const int* in_sizes, int n_in,
                              void* d_out, int out_size)
{
    const float* x     = (const float*)d_in[0];
    const float* w_qkv = (const float*)d_in[1];
    const float* w_out = (const float*)d_in[2];
    const float* b_out = (const float*)d_in[3];
    const float* ln1_g = (const float*)d_in[4];
    const float* ln1_b = (const float*)d_in[5];
    const float* ln2_g = (const float*)d_in[6];
    const float* ln2_b = (const float*)d_in[7];
    const float* w1    = (const float*)d_in[8];
    const float* b1    = (const float*)d_in[9];
    const float* w2    = (const float*)d_in[10];
    const float* b2    = (const float*)d_in[11];
    float* out = (float*)d_out;

    float *p_xn, *p_qkv, *p_att, *p_x2, *p_h;
    cudaGetSymbolAddress((void**)&p_xn,  g_xn);
    cudaGetSymbolAddress((void**)&p_qkv, g_qkv);
    cudaGetSymbolAddress((void**)&p_att, g_att);
    cudaGetSymbolAddress((void**)&p_x2,  g_x2);
    cudaGetSymbolAddress((void**)&p_h,   g_h);
    float* p_xn2 = p_xn;

    // 1. LN1
    ln_kernel<<<MTOK, 256>>>(x, ln1_g, ln1_b, p_xn);
    // 2. QKV GEMM
    sgemm_hc<0><<<dim3(QKV_N / 128, MTOK / 128), 256>>>(p_xn, w_qkv, p_qkv,
                                                        nullptr, nullptr,
                                                        MTOK, QKV_N, EMB);
    // 3. Attention (tensor-core, tf32)
    attn_tc<<<dim3(SEQ / 64, NH, BATCH), 128>>>(p_qkv, p_att);
    // 4. Output projection + bias + residual(x)
    sgemm_hc<1><<<dim3(EMB / 128, MTOK / 128), 256>>>(p_att, w_out, p_x2,
                                                      b_out, x,
                                                      MTOK, EMB, EMB);
    // 5. LN2
    ln_kernel<<<MTOK, 256>>>(p_x2, ln2_g, ln2_b, p_xn2);
    // 6. FFN1 + bias + exact GELU
    sgemm_hc<2><<<dim3(FFD / 128, MTOK / 128), 256>>>(p_xn2, w1, p_h,
                                                      b1, nullptr,
                                                      MTOK, FFD, EMB);
    // 7. FFN2 + bias + residual(x2) -> out
    sgemm_hc<1><<<dim3(EMB / 128, MTOK / 128), 256>>>(p_h, w2, out,
                                                      b2, p_x2,
                                                      MTOK, EMB, FFD);
}

// round 9
// speedup vs baseline: 5.7143x; 1.4164x over previous
#include <cuda_runtime.h>
#include <cuda_fp16.h>
#include <math.h>
#include <stdint.h>

// Problem constants
#define BATCH 2
#define SEQ   2048
#define EMB   1024
#define NH    16
#define HD    64
#define FFD   4096
#define MTOK  (BATCH*SEQ)     // 4096
#define QKV_N (3*EMB)         // 3072
#define LN_EPS 1e-5f

// Scratch (device globals; allocations are forbidden in kernel_launch).
__device__ float  g_qkv[MTOK*QKV_N];     // fp32 (attention input)
__device__ float  g_x2 [MTOK*EMB];       // fp32 residual-1
__device__ __half g_xn [MTOK*EMB];       // LN out (fp16), reused for LN2
__device__ __half g_att[MTOK*EMB];       // attention out (fp16)
__device__ __half g_h  [MTOK*FFD];       // FFN1 out (fp16)
__device__ __half g_wqkv[EMB*QKV_N];     // fp16 weights
__device__ __half g_wout[EMB*EMB];
__device__ __half g_w1  [EMB*FFD];
__device__ __half g_w2  [FFD*EMB];

// ---------------------------------------------------------------------------
// helpers
// ---------------------------------------------------------------------------
__device__ __forceinline__ uint32_t f2tf(float f)
{
    uint32_t r;
    asm("cvt.rna.tf32.f32 %0, %1;" : "=r"(r) : "f"(f));
    return r;
}
__device__ __forceinline__ uint32_t pack2h(float lo, float hi)
{
    uint32_t r;
    asm("cvt.rn.f16x2.f32 %0, %1, %2;" : "=r"(r) : "f"(hi), "f"(lo));
    return r;
}
__device__ __forceinline__ void mma_tf32(float* d, const uint32_t* a, const uint32_t* b)
{
    asm volatile(
        "mma.sync.aligned.m16n8k8.row.col.f32.tf32.tf32.f32 "
        "{%0,%1,%2,%3}, {%4,%5,%6,%7}, {%8,%9}, {%0,%1,%2,%3};\n"
        : "+f"(d[0]), "+f"(d[1]), "+f"(d[2]), "+f"(d[3])
        : "r"(a[0]), "r"(a[1]), "r"(a[2]), "r"(a[3]), "r"(b[0]), "r"(b[1]));
}
__device__ __forceinline__ void mma_f16(float* d, const uint32_t* a, const uint32_t* b)
{
    asm volatile(
        "mma.sync.aligned.m16n8k16.row.col.f32.f16.f16.f32 "
        "{%0,%1,%2,%3}, {%4,%5,%6,%7}, {%8,%9}, {%0,%1,%2,%3};\n"
        : "+f"(d[0]), "+f"(d[1]), "+f"(d[2]), "+f"(d[3])
        : "r"(a[0]), "r"(a[1]), "r"(a[2]), "r"(a[3]), "r"(b[0]), "r"(b[1]));
}
__device__ __forceinline__ void ldsm4(uint32_t* r, uint32_t addr)
{
    asm volatile("ldmatrix.sync.aligned.m8n8.x4.shared.b16 {%0,%1,%2,%3}, [%4];"
                 : "=r"(r[0]), "=r"(r[1]), "=r"(r[2]), "=r"(r[3]) : "r"(addr));
}
__device__ __forceinline__ void ldsm4t(uint32_t* r, uint32_t addr)
{
    asm volatile("ldmatrix.sync.aligned.m8n8.x4.trans.shared.b16 {%0,%1,%2,%3}, [%4];"
                 : "=r"(r[0]), "=r"(r[1]), "=r"(r[2]), "=r"(r[3]) : "r"(addr));
}
__device__ __forceinline__ void cpa16(uint32_t dst, const void* src)
{
    asm volatile("cp.async.ca.shared.global [%0], [%1], 16;" :: "r"(dst), "l"(src));
}
#define CP_COMMIT() asm volatile("cp.async.commit_group;")
#define CP_WAIT1()  asm volatile("cp.async.wait_group 1;")

// ---------------------------------------------------------------------------
// fp32 -> fp16 conversion (weights), 8 elems/thread
// ---------------------------------------------------------------------------
__global__ __launch_bounds__(256) void cvt_h(const float* __restrict__ src,
                                             __half* __restrict__ dst, int n)
{
    int i = (blockIdx.x * 256 + threadIdx.x) * 8;
    if (i >= n) return;
    float4 f0 = *(const float4*)&src[i];
    float4 f1 = *(const float4*)&src[i + 4];
    uint4 u;
    u.x = pack2h(f0.x, f0.y); u.y = pack2h(f0.z, f0.w);
    u.z = pack2h(f1.x, f1.y); u.w = pack2h(f1.z, f1.w);
    *(uint4*)&dst[i] = u;
}

// ---------------------------------------------------------------------------
// LayerNorm, fp16 output
// ---------------------------------------------------------------------------
__global__ __launch_bounds__(256) void ln_h(const float* __restrict__ x,
                                            const float* __restrict__ g,
                                            const float* __restrict__ b,
                                            __half* __restrict__ out)
{
    int row = blockIdx.x;
    const float* xr = x + (size_t)row * EMB;
    float v[4];
    float sum = 0.f, sq = 0.f;
#pragma unroll
    for (int i = 0; i < 4; i++) {
        v[i] = xr[threadIdx.x + i * 256];
        sum += v[i];
        sq  += v[i] * v[i];
    }
#pragma unroll
    for (int o = 16; o > 0; o >>= 1) {
        sum += __shfl_xor_sync(0xffffffffu, sum, o);
        sq  += __shfl_xor_sync(0xffffffffu, sq,  o);
    }
    __shared__ float s1[8], s2[8];
    int w = threadIdx.x >> 5, l = threadIdx.x & 31;
    if (l == 0) { s1[w] = sum; s2[w] = sq; }
    __syncthreads();
    sum = 0.f; sq = 0.f;
#pragma unroll
    for (int i = 0; i < 8; i++) { sum += s1[i]; sq += s2[i]; }
    float mu  = sum * (1.0f / EMB);
    float var = sq * (1.0f / EMB) - mu * mu;
    float inv = rsqrtf(var + LN_EPS);
    __half* orow = out + (size_t)row * EMB;
#pragma unroll
    for (int i = 0; i < 4; i++) {
        int c = threadIdx.x + i * 256;
        orow[c] = __float2half((v[i] - mu) * inv * g[c] + b[c]);
    }
}

// ---------------------------------------------------------------------------
// fp16 async-pipelined tensor-core GEMM.
// 128x128x32 CTA tile, 8 warps (2x4), warp tile 64x32, mma.m16n8k16,
// 3-stage cp.async pipeline, ldmatrix fragment loads, XOR-swizzled smem.
// A[M,K], B[K,N] row-major fp16.  EPI: 0 ->fp32 C; 1 ->fp32 C +bias+res;
// 2 ->fp16 C +bias+GELU(exact).  Requires M%128==0, N%128==0, K%32==0.
// ---------------------------------------------------------------------------
template <int EPI>
__global__ __launch_bounds__(256, 2) void gemm16(const __half* __restrict__ A,
                                                 const __half* __restrict__ B,
                                                 void* __restrict__ Cv,
                                                 const float* __restrict__ bias,
                                                 const float* __restrict__ res,
                                                 int M, int N, int K)
{
    __shared__ __half As[3][128][32];   // 8KB/stage, swizzle chunk^((row>>1)&3)
    __shared__ __half Bs[3][32][128];   // 8KB/stage, swizzle chunk^(row&7)

    const int tid = threadIdx.x;
    const int m0 = blockIdx.y * 128;
    const int n0 = blockIdx.x * 128;

    const int warpId = tid >> 5;
    const int lane   = tid & 31;
    const int wm = (warpId & 1) * 64;
    const int wn = (warpId >> 1) * 32;
    const int g  = lane >> 2;
    const int t3 = lane & 3;

    const uint32_t aSm = (uint32_t)__cvta_generic_to_shared(&As[0][0][0]);
    const uint32_t bSm = (uint32_t)__cvta_generic_to_shared(&Bs[0][0][0]);

    // ldmatrix lane-address components
    const int lrow = lane & 15;       // row within 16-row tile (A) / k-tile (B)
    const int csel = lane >> 4;       // chunk select (0/1)

    // fill mappings (2 x 16B cp.async each for A and B per thread)
    const int fAr = tid >> 2, fAc = tid & 3;
    const int fBk = tid >> 4, fBc = tid & 15;

    const int T = K >> 5;

    // acc[mi][ni][c]
    float acc[4][4][4];
#pragma unroll
    for (int i = 0; i < 4; i++)
#pragma unroll
        for (int j = 0; j < 4; j++)
#pragma unroll
            for (int c = 0; c < 4; c++) acc[i][j][c] = 0.f;

#define FILL(st, kt)                                                            \
    do {                                                                        \
        int r0_ = fAr, r1_ = fAr + 64;                                          \
        cpa16(aSm + (st)*8192 + r0_*64 + ((fAc ^ ((r0_>>1)&3))<<4),             \
              A + (size_t)(m0 + r0_) * K + (kt)*32 + fAc*8);                    \
        cpa16(aSm + (st)*8192 + r1_*64 + ((fAc ^ ((r1_>>1)&3))<<4),             \
              A + (size_t)(m0 + r1_) * K + (kt)*32 + fAc*8);                    \
        int k0_ = fBk, k1_ = fBk + 16;                                          \
        cpa16(bSm + (st)*8192 + k0_*256 + ((fBc ^ (k0_&7))<<4),                 \
              B + (size_t)((kt)*32 + k0_) * N + n0 + fBc*8);                    \
        cpa16(bSm + (st)*8192 + k1_*256 + ((fBc ^ (k1_&7))<<4),                 \
              B + (size_t)((kt)*32 + k1_) * N + n0 + fBc*8);                    \
    } while (0)

    FILL(0, 0); CP_COMMIT();
    FILL(1, 1); CP_COMMIT();

    for (int t = 0; t < T; t++) {
        CP_WAIT1();
        __syncthreads();
        const int st = t % 3;
        const uint32_t aStage = aSm + st * 8192;
        const uint32_t bStage = bSm + st * 8192;

#pragma unroll
        for (int kb = 0; kb < 2; kb++) {
            uint32_t af[4][4];
#pragma unroll
            for (int mi = 0; mi < 4; mi++) {
                int row = wm + mi * 16 + lrow;
                uint32_t ad = aStage + row * 64
                            + ((((kb << 1) | csel) ^ ((row >> 1) & 3)) << 4);
                ldsm4(af[mi], ad);
            }
            uint32_t bfr[2][4];
#pragma unroll
            for (int p = 0; p < 2; p++) {
                int krow = kb * 16 + lrow;
                int nch  = (wn >> 3) + p * 2 + csel;
                uint32_t bd = bStage + krow * 256 + ((nch ^ (krow & 7)) << 4);
                ldsm4t(bfr[p], bd);
            }
#pragma unroll
            for (int mi = 0; mi < 4; mi++)
#pragma unroll
                for (int ni = 0; ni < 4; ni++)
                    mma_f16(acc[mi][ni], af[mi], &bfr[ni >> 1][(ni & 1) * 2]);
        }

        if (t + 2 < T) FILL((t + 2) % 3, t + 2);
        CP_COMMIT();
    }
#undef FILL

    // Epilogue: c0,c1 at (row, 2*t3+{0,1}); c2,c3 at (row+8, same cols)
#pragma unroll
    for (int mi = 0; mi < 4; mi++) {
#pragma unroll
        for (int rr = 0; rr < 2; rr++) {
            int row = m0 + wm + mi * 16 + g + rr * 8;
#pragma unroll
            for (int ni = 0; ni < 4; ni++) {
                int col = n0 + wn + ni * 8 + 2 * t3;
                float v0 = acc[mi][ni][rr * 2 + 0];
                float v1 = acc[mi][ni][rr * 2 + 1];
                if (EPI >= 1) { v0 += bias[col]; v1 += bias[col + 1]; }
                if (EPI == 1) {
                    const float* Rp = res + (size_t)row * N + col;
                    v0 += Rp[0]; v1 += Rp[1];
                    float* C = (float*)Cv;
                    *(float2*)&C[(size_t)row * N + col] = make_float2(v0, v1);
                } else if (EPI == 2) {
                    v0 = 0.5f * v0 * (1.0f + erff(v0 * 0.70710678118654752f));
                    v1 = 0.5f * v1 * (1.0f + erff(v1 * 0.70710678118654752f));
                    uint32_t* Ch = (uint32_t*)Cv;
                    Ch[((size_t)row * N + col) >> 1] = pack2h(v0, v1);
                } else {
                    float* C = (float*)Cv;
                    *(float2*)&C[(size_t)row * N + col] = make_float2(v0, v1);
                }
            }
        }
    }
}

// ---------------------------------------------------------------------------
// Tensor-core flash attention (tf32 in, fp16 out).
// grid=(SEQ/64, NH, BATCH), 128 threads (4 warps).
// ---------------------------------------------------------------------------
__global__ __launch_bounds__(128) void attn_tc(const float* __restrict__ qkv,
                                               __half* __restrict__ out)
{
    __shared__ uint32_t Ks[64][68];   // K tile (tf32), then reused as P
    __shared__ uint32_t Vs[64][72];   // V tile (tf32)

    const int qb = blockIdx.x;
    const int h  = blockIdx.y;
    const int b  = blockIdx.z;
    const int tid  = threadIdx.x;
    const int w    = tid >> 5;
    const int lane = tid & 31;
    const int g  = lane >> 2;
    const int t3 = lane & 3;

    const float SCL = 2.8284271247461903f;  // 64^0.25
    const float* base = qkv + (size_t)b * SEQ * QKV_N + h * HD;

    const int qr0 = qb * 64 + w * 16 + g;
    const float* q0 = base + (size_t)qr0 * QKV_N;
    const float* q8 = q0 + (size_t)8 * QKV_N;

    uint32_t qf[8][4];
#pragma unroll
    for (int kb = 0; kb < 8; kb++) {
        qf[kb][0] = f2tf(q0[kb * 8 + t3]     * SCL);
        qf[kb][1] = f2tf(q8[kb * 8 + t3]     * SCL);
        qf[kb][2] = f2tf(q0[kb * 8 + t3 + 4] * SCL);
        qf[kb][3] = f2tf(q8[kb * 8 + t3 + 4] * SCL);
    }

    float oacc[8][4];
#pragma unroll
    for (int i = 0; i < 8; i++)
#pragma unroll
        for (int c = 0; c < 4; c++) oacc[i][c] = 0.f;
    float m0 = -1e30f, m1 = -1e30f, l0 = 0.f, l1 = 0.f;

    for (int kt = 0; kt < SEQ / 64; kt++) {
        __syncthreads();
        for (int i = tid; i < 64 * 16; i += 128) {
            int r = i >> 4, c = (i & 15) << 2;
            const float* kp = base + EMB + (size_t)(kt * 64 + r) * QKV_N + c;
            float4 k4 = *(const float4*)kp;
            float4 v4 = *(const float4*)(kp + EMB);
            uint4 ku, vu;
            ku.x=f2tf(k4.x); ku.y=f2tf(k4.y); ku.z=f2tf(k4.z); ku.w=f2tf(k4.w);
            vu.x=f2tf(v4.x); vu.y=f2tf(v4.y); vu.z=f2tf(v4.z); vu.w=f2tf(v4.w);
            *(uint4*)&Ks[r][c] = ku;
            *(uint4*)&Vs[r][c] = vu;
        }
        __syncthreads();

        float sacc[8][4];
#pragma unroll
        for (int i = 0; i < 8; i++)
#pragma unroll
            for (int c = 0; c < 4; c++) sacc[i][c] = 0.f;

#pragma unroll
        for (int kb = 0; kb < 8; kb++) {
#pragma unroll
            for (int ni = 0; ni < 8; ni++) {
                uint32_t bf[2];
                bf[0] = Ks[ni * 8 + g][kb * 8 + t3];
                bf[1] = Ks[ni * 8 + g][kb * 8 + t3 + 4];
                mma_tf32(sacc[ni], qf[kb], bf);
            }
        }

        float rm0 = -1e30f, rm1 = -1e30f;
#pragma unroll
        for (int ni = 0; ni < 8; ni++) {
            rm0 = fmaxf(rm0, fmaxf(sacc[ni][0], sacc[ni][1]));
            rm1 = fmaxf(rm1, fmaxf(sacc[ni][2], sacc[ni][3]));
        }
        rm0 = fmaxf(rm0, __shfl_xor_sync(0xffffffffu, rm0, 1));
        rm0 = fmaxf(rm0, __shfl_xor_sync(0xffffffffu, rm0, 2));
        rm1 = fmaxf(rm1, __shfl_xor_sync(0xffffffffu, rm1, 1));
        rm1 = fmaxf(rm1, __shfl_xor_sync(0xffffffffu, rm1, 2));
        float mn0 = fmaxf(m0, rm0), mn1 = fmaxf(m1, rm1);
        float cr0 = __expf(m0 - mn0), cr1 = __expf(m1 - mn1);
        float rs0 = 0.f, rs1 = 0.f;
#pragma unroll
        for (int ni = 0; ni < 8; ni++) {
            sacc[ni][0] = __expf(sacc[ni][0] - mn0);
            sacc[ni][1] = __expf(sacc[ni][1] - mn0);
            sacc[ni][2] = __expf(sacc[ni][2] - mn1);
            sacc[ni][3] = __expf(sacc[ni][3] - mn1);
            rs0 += sacc[ni][0] + sacc[ni][1];
            rs1 += sacc[ni][2] + sacc[ni][3];
        }
        rs0 += __shfl_xor_sync(0xffffffffu, rs0, 1);
        rs0 += __shfl_xor_sync(0xffffffffu, rs0, 2);
        rs1 += __shfl_xor_sync(0xffffffffu, rs1, 1);
        rs1 += __shfl_xor_sync(0xffffffffu, rs1, 2);
        l0 = l0 * cr0 + rs0;  m0 = mn0;
        l1 = l1 * cr1 + rs1;  m1 = mn1;
#pragma unroll
        for (int di = 0; di < 8; di++) {
            oacc[di][0] *= cr0; oacc[di][1] *= cr0;
            oacc[di][2] *= cr1; oacc[di][3] *= cr1;
        }

        __syncthreads();
        const int pr = w * 16 + g;
#pragma unroll
        for (int ni = 0; ni < 8; ni++) {
            Ks[pr    ][ni * 8 + 2 * t3]     = f2tf(sacc[ni][0]);
            Ks[pr    ][ni * 8 + 2 * t3 + 1] = f2tf(sacc[ni][1]);
            Ks[pr + 8][ni * 8 + 2 * t3]     = f2tf(sacc[ni][2]);
            Ks[pr + 8][ni * 8 + 2 * t3 + 1] = f2tf(sacc[ni][3]);
        }
        __syncwarp();

#pragma unroll
        for (int kc = 0; kc < 8; kc++) {
            uint32_t pa[4];
            pa[0] = Ks[pr    ][kc * 8 + t3];
            pa[1] = Ks[pr + 8][kc * 8 + t3];
            pa[2] = Ks[pr    ][kc * 8 + t3 + 4];
            pa[3] = Ks[pr + 8][kc * 8 + t3 + 4];
#pragma unroll
            for (int di = 0; di < 8; di++) {
                uint32_t bf[2];
                bf[0] = Vs[kc * 8 + t3    ][di * 8 + g];
                bf[1] = Vs[kc * 8 + t3 + 4][di * 8 + g];
                mma_tf32(oacc[di], pa, bf);
            }
        }
    }

    float inv0 = 1.0f / l0, inv1 = 1.0f / l1;
    __half* o0 = out + (size_t)(b * SEQ + qr0) * EMB + h * HD;
    __half* o8 = o0 + (size_t)8 * EMB;
#pragma unroll
    for (int di = 0; di < 8; di++) {
        int col = di * 8 + 2 * t3;
        *(uint32_t*)&o0[col] = pack2h(oacc[di][0] * inv0, oacc[di][1] * inv0);
        *(uint32_t*)&o8[col] = pack2h(oacc[di][2] * inv1, oacc[di][3] * inv1);
    }
}

// ---------------------------------------------------------------------------
// Launch
// ---------------------------------------------------------------------------
extern "C" void kernel_launch(void* const* d_in, const int* in_sizes, int n_in,
                              void* d_out, int out_size)
{
    const float* x     = (const float*)d_in[0];
    const float* w_qkv = (const float*)d_in[1];
    const float* w_out = (const float*)d_in[2];
    const float* b_out = (const float*)d_in[3];
    const float* ln1_g = (const float*)d_in[4];
    const float* ln1_b = (const float*)d_in[5];
    const float* ln2_g = (const float*)d_in[6];
    const float* ln2_b = (const float*)d_in[7];
    const float* w1    = (const float*)d_in[8];
    const float* b1    = (const float*)d_in[9];
    const float* w2    = (const float*)d_in[10];
    const float* b2    = (const float*)d_in[11];
    float* out = (float*)d_out;

    float  *p_qkv, *p_x2;
    __half *p_xn, *p_att, *p_h, *p_wqkv, *p_wout, *p_w1, *p_w2;
    cudaGetSymbolAddress((void**)&p_qkv,  g_qkv);
    cudaGetSymbolAddress((void**)&p_x2,   g_x2);
    cudaGetSymbolAddress((void**)&p_xn,   g_xn);
    cudaGetSymbolAddress((void**)&p_att,  g_att);
    cudaGetSymbolAddress((void**)&p_h,    g_h);
    cudaGetSymbolAddress((void**)&p_wqkv, g_wqkv);
    cudaGetSymbolAddress((void**)&p_wout, g_wout);
    cudaGetSymbolAddress((void**)&p_w1,   g_w1);
    cudaGetSymbolAddress((void**)&p_w2,   g_w2);

    // 0. weight conversions (fp32 -> fp16)
    cvt_h<<<(EMB*QKV_N)/2048, 256>>>(w_qkv, p_wqkv, EMB*QKV_N);
    cvt_h<<<(EMB*EMB)/2048,  256>>>(w_out, p_wout, EMB*EMB);
    cvt_h<<<(EMB*FFD)/2048,  256>>>(w1,    p_w1,   EMB*FFD);
    cvt_h<<<(FFD*EMB)/2048,  256>>>(w2,    p_w2,   FFD*EMB);

    // 1. LN1 -> fp16
    ln_h<<<MTOK, 256>>>(x, ln1_g, ln1_b, p_xn);
    // 2. QKV GEMM -> fp32
    gemm16<0><<<dim3(QKV_N / 128, MTOK / 128), 256>>>(p_xn, p_wqkv, p_qkv,
                                                      nullptr, nullptr,
                                                      MTOK, QKV_N, EMB);
    // 3. Attention -> fp16
    attn_tc<<<dim3(SEQ / 64, NH, BATCH), 128>>>(p_qkv, p_att);
    // 4. Output projection + bias + residual(x) -> fp32
    gemm16<1><<<dim3(EMB / 128, MTOK / 128), 256>>>(p_att, p_wout, p_x2,
                                                    b_out, x,
                                                    MTOK, EMB, EMB);
    // 5. LN2 -> fp16
    ln_h<<<MTOK, 256>>>(p_x2, ln2_g, ln2_b, p_xn);
    // 6. FFN1 + bias + GELU -> fp16
    gemm16<2><<<dim3(FFD / 128, MTOK / 128), 256>>>(p_xn, p_w1, p_h,
                                                    b1, nullptr,
                                                    MTOK, FFD, EMB);
    // 7. FFN2 + bias + residual(x2) -> out (fp32)
    gemm16<1><<<dim3(EMB / 128, MTOK / 128), 256>>>(p_h, p_w2, out,
                                                    b2, p_x2,
                                                    MTOK, EMB, FFD);
}

// round 11
// speedup vs baseline: 6.6354x; 1.1612x over previous
#include <cuda_runtime.h>
#include <cuda_fp16.h>
#include <math.h>
#include <stdint.h>

// Problem constants
#define BATCH 2
#define SEQ   2048
#define EMB   1024
#define NH    16
#define HD    64
#define FFD   4096
#define MTOK  (BATCH*SEQ)     // 4096
#define QKV_N (3*EMB)         // 3072
#define LN_EPS 1e-5f

// Scratch (device globals; allocations are forbidden in kernel_launch).
__device__ __half g_qkv[MTOK*QKV_N];     // fp16 QKV (attention input)
__device__ float  g_x2 [MTOK*EMB];       // fp32 residual-1
__device__ __half g_xn [MTOK*EMB];       // LN out (fp16), reused for LN2
__device__ __half g_att[MTOK*EMB];       // attention out (fp16)
__device__ __half g_h  [MTOK*FFD];       // FFN1 out (fp16)
__device__ __half g_wqkv[EMB*QKV_N];     // fp16 weights
__device__ __half g_wout[EMB*EMB];
__device__ __half g_w1  [EMB*FFD];
__device__ __half g_w2  [FFD*EMB];

// ---------------------------------------------------------------------------
// helpers
// ---------------------------------------------------------------------------
__device__ __forceinline__ uint32_t pack2h(float lo, float hi)
{
    uint32_t r;
    asm("cvt.rn.f16x2.f32 %0, %1, %2;" : "=r"(r) : "f"(hi), "f"(lo));
    return r;
}
__device__ __forceinline__ void mma_f16(float* d, const uint32_t* a, const uint32_t* b)
{
    asm volatile(
        "mma.sync.aligned.m16n8k16.row.col.f32.f16.f16.f32 "
        "{%0,%1,%2,%3}, {%4,%5,%6,%7}, {%8,%9}, {%0,%1,%2,%3};\n"
        : "+f"(d[0]), "+f"(d[1]), "+f"(d[2]), "+f"(d[3])
        : "r"(a[0]), "r"(a[1]), "r"(a[2]), "r"(a[3]), "r"(b[0]), "r"(b[1]));
}
__device__ __forceinline__ void ldsm4(uint32_t* r, uint32_t addr)
{
    asm volatile("ldmatrix.sync.aligned.m8n8.x4.shared.b16 {%0,%1,%2,%3}, [%4];"
                 : "=r"(r[0]), "=r"(r[1]), "=r"(r[2]), "=r"(r[3]) : "r"(addr));
}
__device__ __forceinline__ void ldsm4t(uint32_t* r, uint32_t addr)
{
    asm volatile("ldmatrix.sync.aligned.m8n8.x4.trans.shared.b16 {%0,%1,%2,%3}, [%4];"
                 : "=r"(r[0]), "=r"(r[1]), "=r"(r[2]), "=r"(r[3]) : "r"(addr));
}
__device__ __forceinline__ void cpa16(uint32_t dst, const void* src)
{
    asm volatile("cp.async.ca.shared.global [%0], [%1], 16;" :: "r"(dst), "l"(src));
}
#define CP_COMMIT() asm volatile("cp.async.commit_group;")
#define CP_WAIT1()  asm volatile("cp.async.wait_group 1;")

// ---------------------------------------------------------------------------
// fp32 -> fp16 conversion (weights), 8 elems/thread
// ---------------------------------------------------------------------------
__global__ __launch_bounds__(256) void cvt_h(const float* __restrict__ src,
                                             __half* __restrict__ dst, int n)
{
    int i = (blockIdx.x * 256 + threadIdx.x) * 8;
    if (i >= n) return;
    float4 f0 = *(const float4*)&src[i];
    float4 f1 = *(const float4*)&src[i + 4];
    uint4 u;
    u.x = pack2h(f0.x, f0.y); u.y = pack2h(f0.z, f0.w);
    u.z = pack2h(f1.x, f1.y); u.w = pack2h(f1.z, f1.w);
    *(uint4*)&dst[i] = u;
}

// ---------------------------------------------------------------------------
// LayerNorm, fp16 output
// ---------------------------------------------------------------------------
__global__ __launch_bounds__(256) void ln_h(const float* __restrict__ x,
                                            const float* __restrict__ g,
                                            const float* __restrict__ b,
                                            __half* __restrict__ out)
{
    int row = blockIdx.x;
    const float* xr = x + (size_t)row * EMB;
    float v[4];
    float sum = 0.f, sq = 0.f;
#pragma unroll
    for (int i = 0; i < 4; i++) {
        v[i] = xr[threadIdx.x + i * 256];
        sum += v[i];
        sq  += v[i] * v[i];
    }
#pragma unroll
    for (int o = 16; o > 0; o >>= 1) {
        sum += __shfl_xor_sync(0xffffffffu, sum, o);
        sq  += __shfl_xor_sync(0xffffffffu, sq,  o);
    }
    __shared__ float s1[8], s2[8];
    int w = threadIdx.x >> 5, l = threadIdx.x & 31;
    if (l == 0) { s1[w] = sum; s2[w] = sq; }
    __syncthreads();
    sum = 0.f; sq = 0.f;
#pragma unroll
    for (int i = 0; i < 8; i++) { sum += s1[i]; sq += s2[i]; }
    float mu  = sum * (1.0f / EMB);
    float var = sq * (1.0f / EMB) - mu * mu;
    float inv = rsqrtf(var + LN_EPS);
    __half* orow = out + (size_t)row * EMB;
#pragma unroll
    for (int i = 0; i < 4; i++) {
        int c = threadIdx.x + i * 256;
        orow[c] = __float2half((v[i] - mu) * inv * g[c] + b[c]);
    }
}

// ---------------------------------------------------------------------------
// fp16 async-pipelined tensor-core GEMM (validated R9).
// EPI: 0 ->fp32 C; 1 ->fp32 C +bias+res; 2 ->fp16 C +bias+GELU; 3 ->fp16 C.
// ---------------------------------------------------------------------------
template <int EPI>
__global__ __launch_bounds__(256, 2) void gemm16(const __half* __restrict__ A,
                                                 const __half* __restrict__ B,
                                                 void* __restrict__ Cv,
                                                 const float* __restrict__ bias,
                                                 const float* __restrict__ res,
                                                 int M, int N, int K)
{
    __shared__ __half As[3][128][32];   // 8KB/stage, swizzle chunk^((row>>1)&3)
    __shared__ __half Bs[3][32][128];   // 8KB/stage, swizzle chunk^(row&7)

    const int tid = threadIdx.x;
    const int m0 = blockIdx.y * 128;
    const int n0 = blockIdx.x * 128;

    const int warpId = tid >> 5;
    const int lane   = tid & 31;
    const int wm = (warpId & 1) * 64;
    const int wn = (warpId >> 1) * 32;
    const int g  = lane >> 2;
    const int t3 = lane & 3;

    const uint32_t aSm = (uint32_t)__cvta_generic_to_shared(&As[0][0][0]);
    const uint32_t bSm = (uint32_t)__cvta_generic_to_shared(&Bs[0][0][0]);

    const int lrow = lane & 15;
    const int csel = lane >> 4;

    const int fAr = tid >> 2, fAc = tid & 3;
    const int fBk = tid >> 4, fBc = tid & 15;

    const int T = K >> 5;

    float acc[4][4][4];
#pragma unroll
    for (int i = 0; i < 4; i++)
#pragma unroll
        for (int j = 0; j < 4; j++)
#pragma unroll
            for (int c = 0; c < 4; c++) acc[i][j][c] = 0.f;

#define FILL(st, kt)                                                            \
    do {                                                                        \
        int r0_ = fAr, r1_ = fAr + 64;                                          \
        cpa16(aSm + (st)*8192 + r0_*64 + ((fAc ^ ((r0_>>1)&3))<<4),             \
              A + (size_t)(m0 + r0_) * K + (kt)*32 + fAc*8);                    \
        cpa16(aSm + (st)*8192 + r1_*64 + ((fAc ^ ((r1_>>1)&3))<<4),             \
              A + (size_t)(m0 + r1_) * K + (kt)*32 + fAc*8);                    \
        int k0_ = fBk, k1_ = fBk + 16;                                          \
        cpa16(bSm + (st)*8192 + k0_*256 + ((fBc ^ (k0_&7))<<4),                 \
              B + (size_t)((kt)*32 + k0_) * N + n0 + fBc*8);                    \
        cpa16(bSm + (st)*8192 + k1_*256 + ((fBc ^ (k1_&7))<<4),                 \
              B + (size_t)((kt)*32 + k1_) * N + n0 + fBc*8);                    \
    } while (0)

    FILL(0, 0); CP_COMMIT();
    FILL(1, 1); CP_COMMIT();

    for (int t = 0; t < T; t++) {
        CP_WAIT1();
        __syncthreads();
        const int st = t % 3;
        const uint32_t aStage = aSm + st * 8192;
        const uint32_t bStage = bSm + st * 8192;

#pragma unroll
        for (int kb = 0; kb < 2; kb++) {
            uint32_t af[4][4];
#pragma unroll
            for (int mi = 0; mi < 4; mi++) {
                int row = wm + mi * 16 + lrow;
                uint32_t ad = aStage + row * 64
                            + ((((kb << 1) | csel) ^ ((row >> 1) & 3)) << 4);
                ldsm4(af[mi], ad);
            }
            uint32_t bfr[2][4];
#pragma unroll
            for (int p = 0; p < 2; p++) {
                int krow = kb * 16 + lrow;
                int nch  = (wn >> 3) + p * 2 + csel;
                uint32_t bd = bStage + krow * 256 + ((nch ^ (krow & 7)) << 4);
                ldsm4t(bfr[p], bd);
            }
#pragma unroll
            for (int mi = 0; mi < 4; mi++)
#pragma unroll
                for (int ni = 0; ni < 4; ni++)
                    mma_f16(acc[mi][ni], af[mi], &bfr[ni >> 1][(ni & 1) * 2]);
        }

        if (t + 2 < T) FILL((t + 2) % 3, t + 2);
        CP_COMMIT();
    }
#undef FILL

#pragma unroll
    for (int mi = 0; mi < 4; mi++) {
#pragma unroll
        for (int rr = 0; rr < 2; rr++) {
            int row = m0 + wm + mi * 16 + g + rr * 8;
#pragma unroll
            for (int ni = 0; ni < 4; ni++) {
                int col = n0 + wn + ni * 8 + 2 * t3;
                float v0 = acc[mi][ni][rr * 2 + 0];
                float v1 = acc[mi][ni][rr * 2 + 1];
                if (EPI == 1 || EPI == 2) { v0 += bias[col]; v1 += bias[col + 1]; }
                if (EPI == 1) {
                    const float* Rp = res + (size_t)row * N + col;
                    v0 += Rp[0]; v1 += Rp[1];
                    float* C = (float*)Cv;
                    *(float2*)&C[(size_t)row * N + col] = make_float2(v0, v1);
                } else if (EPI == 2) {
                    v0 = 0.5f * v0 * (1.0f + erff(v0 * 0.70710678118654752f));
                    v1 = 0.5f * v1 * (1.0f + erff(v1 * 0.70710678118654752f));
                    uint32_t* Ch = (uint32_t*)Cv;
                    Ch[((size_t)row * N + col) >> 1] = pack2h(v0, v1);
                } else if (EPI == 3) {
                    uint32_t* Ch = (uint32_t*)Cv;
                    Ch[((size_t)row * N + col) >> 1] = pack2h(v0, v1);
                } else {
                    float* C = (float*)Cv;
                    *(float2*)&C[(size_t)row * N + col] = make_float2(v0, v1);
                }
            }
        }
    }
}

// ---------------------------------------------------------------------------
// fp16 tensor-core flash attention. grid=(SEQ/64, NH, BATCH), 128 threads.
// Each warp owns 16 q-rows; Q held as fp16 A-fragments in registers.
// S = Q.K^T via m16n8k16 (K B-frags as u32 smem reads); logits scaled by
// D^0.25 on the fp32 accumulator; P packed fp16 into the Ks buffer;
// O += P.V via m16n8k16 with V B-frags from ldmatrix.x4.trans.
// ---------------------------------------------------------------------------
__global__ __launch_bounds__(128) void attn_h16(const __half* __restrict__ qkv,
                                                __half* __restrict__ out)
{
    __shared__ __half Ks[64][72];   // K tile (rows=token, cols=d); reused as P
    __shared__ __half Vs[64][72];   // V tile (rows=token, cols=d)

    const int qb = blockIdx.x;
    const int h  = blockIdx.y;
    const int b  = blockIdx.z;
    const int tid  = threadIdx.x;
    const int w    = tid >> 5;
    const int lane = tid & 31;
    const int g  = lane >> 2;
    const int t3 = lane & 3;
    const int lrow = lane & 15;
    const int csel = lane >> 4;

    const float SCL = 2.8284271247461903f;  // 64^0.25 applied to logits
    const __half* base = qkv + (size_t)b * SEQ * QKV_N + h * HD;
    const uint32_t vSm = (uint32_t)__cvta_generic_to_shared(&Vs[0][0]);

    const int qr0 = qb * 64 + w * 16 + g;
    const __half* q0 = base + (size_t)qr0 * QKV_N;
    const __half* q8 = q0 + (size_t)8 * QKV_N;

    // Q A-fragments: qf[kc] = {(g,2t3),(g+8,2t3),(g,2t3+8),(g+8,2t3+8)} pairs
    uint32_t qf[4][4];
#pragma unroll
    for (int kc = 0; kc < 4; kc++) {
        qf[kc][0] = *(const uint32_t*)&q0[kc * 16 + 2 * t3];
        qf[kc][1] = *(const uint32_t*)&q8[kc * 16 + 2 * t3];
        qf[kc][2] = *(const uint32_t*)&q0[kc * 16 + 2 * t3 + 8];
        qf[kc][3] = *(const uint32_t*)&q8[kc * 16 + 2 * t3 + 8];
    }

    float oacc[8][4];
#pragma unroll
    for (int i = 0; i < 8; i++)
#pragma unroll
        for (int c = 0; c < 4; c++) oacc[i][c] = 0.f;
    float m0 = -1e30f, m1 = -1e30f, l0 = 0.f, l1 = 0.f;

    for (int kt = 0; kt < SEQ / 64; kt++) {
        __syncthreads();   // previous tile's P/V reads complete
        // Load K,V 64x64 fp16 tiles (16B-vectorized)
        for (int i = tid; i < 64 * 8; i += 128) {
            int r = i >> 3, c = (i & 7) * 8;
            const __half* kp = base + EMB + (size_t)(kt * 64 + r) * QKV_N + c;
            *(uint4*)&Ks[r][c] = *(const uint4*)kp;
            *(uint4*)&Vs[r][c] = *(const uint4*)(kp + EMB);
        }
        __syncthreads();

        // S = Q.K^T (warp: 16 x 64), fp32 accumulate
        float sacc[8][4];
#pragma unroll
        for (int i = 0; i < 8; i++)
#pragma unroll
            for (int c = 0; c < 4; c++) sacc[i][c] = 0.f;

#pragma unroll
        for (int kc = 0; kc < 4; kc++) {
#pragma unroll
            for (int ni = 0; ni < 8; ni++) {
                uint32_t bf[2];
                bf[0] = *(const uint32_t*)&Ks[ni * 8 + g][kc * 16 + 2 * t3];
                bf[1] = *(const uint32_t*)&Ks[ni * 8 + g][kc * 16 + 2 * t3 + 8];
                mma_f16(sacc[ni], qf[kc], bf);
            }
        }

        // Scale logits, online softmax (rows g / g+8, 4-lane shfl reduce)
        float rm0 = -1e30f, rm1 = -1e30f;
#pragma unroll
        for (int ni = 0; ni < 8; ni++) {
            sacc[ni][0] *= SCL; sacc[ni][1] *= SCL;
            sacc[ni][2] *= SCL; sacc[ni][3] *= SCL;
            rm0 = fmaxf(rm0, fmaxf(sacc[ni][0], sacc[ni][1]));
            rm1 = fmaxf(rm1, fmaxf(sacc[ni][2], sacc[ni][3]));
        }
        rm0 = fmaxf(rm0, __shfl_xor_sync(0xffffffffu, rm0, 1));
        rm0 = fmaxf(rm0, __shfl_xor_sync(0xffffffffu, rm0, 2));
        rm1 = fmaxf(rm1, __shfl_xor_sync(0xffffffffu, rm1, 1));
        rm1 = fmaxf(rm1, __shfl_xor_sync(0xffffffffu, rm1, 2));
        float mn0 = fmaxf(m0, rm0), mn1 = fmaxf(m1, rm1);
        float cr0 = __expf(m0 - mn0), cr1 = __expf(m1 - mn1);
        float rs0 = 0.f, rs1 = 0.f;
#pragma unroll
        for (int ni = 0; ni < 8; ni++) {
            sacc[ni][0] = __expf(sacc[ni][0] - mn0);
            sacc[ni][1] = __expf(sacc[ni][1] - mn0);
            sacc[ni][2] = __expf(sacc[ni][2] - mn1);
            sacc[ni][3] = __expf(sacc[ni][3] - mn1);
            rs0 += sacc[ni][0] + sacc[ni][1];
            rs1 += sacc[ni][2] + sacc[ni][3];
        }
        rs0 += __shfl_xor_sync(0xffffffffu, rs0, 1);
        rs0 += __shfl_xor_sync(0xffffffffu, rs0, 2);
        rs1 += __shfl_xor_sync(0xffffffffu, rs1, 1);
        rs1 += __shfl_xor_sync(0xffffffffu, rs1, 2);
        l0 = l0 * cr0 + rs0;  m0 = mn0;
        l1 = l1 * cr1 + rs1;  m1 = mn1;
#pragma unroll
        for (int di = 0; di < 8; di++) {
            oacc[di][0] *= cr0; oacc[di][1] *= cr0;
            oacc[di][2] *= cr1; oacc[di][3] *= cr1;
        }

        __syncthreads();   // all warps finished S-mma reads of Ks
        // Write P (fp16 pairs) into Ks rows [w*16, w*16+16)
        const int pr = w * 16 + g;
#pragma unroll
        for (int ni = 0; ni < 8; ni++) {
            *(uint32_t*)&Ks[pr    ][ni * 8 + 2 * t3] = pack2h(sacc[ni][0], sacc[ni][1]);
            *(uint32_t*)&Ks[pr + 8][ni * 8 + 2 * t3] = pack2h(sacc[ni][2], sacc[ni][3]);
        }
        __syncwarp();

        // O += P.V  (A = P from smem, B = V via ldmatrix.trans)
#pragma unroll
        for (int kc = 0; kc < 4; kc++) {
            uint32_t pa[4];
            pa[0] = *(const uint32_t*)&Ks[pr    ][kc * 16 + 2 * t3];
            pa[1] = *(const uint32_t*)&Ks[pr + 8][kc * 16 + 2 * t3];
            pa[2] = *(const uint32_t*)&Ks[pr    ][kc * 16 + 2 * t3 + 8];
            pa[3] = *(const uint32_t*)&Ks[pr + 8][kc * 16 + 2 * t3 + 8];

            uint32_t bfr[4][4];
#pragma unroll
            for (int p = 0; p < 4; p++) {
                int tok = kc * 16 + lrow;
                uint32_t bd = vSm + tok * 144 + (p * 2 + csel) * 16;
                ldsm4t(bfr[p], bd);
            }
#pragma unroll
            for (int di = 0; di < 8; di++)
                mma_f16(oacc[di], pa, &bfr[di >> 1][(di & 1) * 2]);
        }
    }

    // Normalize and store fp16: out[b, q, h*64 + d]
    float inv0 = 1.0f / l0, inv1 = 1.0f / l1;
    __half* o0 = out + (size_t)(b * SEQ + qr0) * EMB + h * HD;
    __half* o8 = o0 + (size_t)8 * EMB;
#pragma unroll
    for (int di = 0; di < 8; di++) {
        int col = di * 8 + 2 * t3;
        *(uint32_t*)&o0[col] = pack2h(oacc[di][0] * inv0, oacc[di][1] * inv0);
        *(uint32_t*)&o8[col] = pack2h(oacc[di][2] * inv1, oacc[di][3] * inv1);
    }
}

// ---------------------------------------------------------------------------
// Launch
// ---------------------------------------------------------------------------
extern "C" void kernel_launch(void* const* d_in, const int* in_sizes, int n_in,
                              void* d_out, int out_size)
{
    const float* x     = (const float*)d_in[0];
    const float* w_qkv = (const float*)d_in[1];
    const float* w_out = (const float*)d_in[2];
    const float* b_out = (const float*)d_in[3];
    const float* ln1_g = (const float*)d_in[4];
    const float* ln1_b = (const float*)d_in[5];
    const float* ln2_g = (const float*)d_in[6];
    const float* ln2_b = (const float*)d_in[7];
    const float* w1    = (const float*)d_in[8];
    const float* b1    = (const float*)d_in[9];
    const float* w2    = (const float*)d_in[10];
    const float* b2    = (const float*)d_in[11];
    float* out = (float*)d_out;

    float  *p_x2;
    __half *p_qkv, *p_xn, *p_att, *p_h, *p_wqkv, *p_wout, *p_w1, *p_w2;
    cudaGetSymbolAddress((void**)&p_qkv,  g_qkv);
    cudaGetSymbolAddress((void**)&p_x2,   g_x2);
    cudaGetSymbolAddress((void**)&p_xn,   g_xn);
    cudaGetSymbolAddress((void**)&p_att,  g_att);
    cudaGetSymbolAddress((void**)&p_h,    g_h);
    cudaGetSymbolAddress((void**)&p_wqkv, g_wqkv);
    cudaGetSymbolAddress((void**)&p_wout, g_wout);
    cudaGetSymbolAddress((void**)&p_w1,   g_w1);
    cudaGetSymbolAddress((void**)&p_w2,   g_w2);

    // 0. weight conversions (fp32 -> fp16)
    cvt_h<<<(EMB*QKV_N)/2048, 256>>>(w_qkv, p_wqkv, EMB*QKV_N);
    cvt_h<<<(EMB*EMB)/2048,  256>>>(w_out, p_wout, EMB*EMB);
    cvt_h<<<(EMB*FFD)/2048,  256>>>(w1,    p_w1,   EMB*FFD);
    cvt_h<<<(FFD*EMB)/2048,  256>>>(w2,    p_w2,   FFD*EMB);

    // 1. LN1 -> fp16
    ln_h<<<MTOK, 256>>>(x, ln1_g, ln1_b, p_xn);
    // 2. QKV GEMM -> fp16
    gemm16<3><<<dim3(QKV_N / 128, MTOK / 128), 256>>>(p_xn, p_wqkv, p_qkv,
                                                      nullptr, nullptr,
                                                      MTOK, QKV_N, EMB);
    // 3. Attention (fp16 tensor-core) -> fp16
    attn_h16<<<dim3(SEQ / 64, NH, BATCH), 128>>>(p_qkv, p_att);
    // 4. Output projection + bias + residual(x) -> fp32
    gemm16<1><<<dim3(EMB / 128, MTOK / 128), 256>>>(p_att, p_wout, p_x2,
                                                    b_out, x,
                                                    MTOK, EMB, EMB);
    // 5. LN2 -> fp16
    ln_h<<<MTOK, 256>>>(p_x2, ln2_g, ln2_b, p_xn);
    // 6. FFN1 + bias + GELU -> fp16
    gemm16<2><<<dim3(FFD / 128, MTOK / 128), 256>>>(p_xn, p_w1, p_h,
                                                    b1, nullptr,
                                                    MTOK, FFD, EMB);
    // 7. FFN2 + bias + residual(x2) -> out (fp32)
    gemm16<1><<<dim3(EMB / 128, MTOK / 128), 256>>>(p_h, p_w2, out,
                                                    b2, p_x2,
                                                    MTOK, EMB, FFD);
}